// round 7
// baseline (speedup 1.0000x reference)
#include <cuda_runtime.h>
#include <cuda_fp16.h>
#include <cstdint>
#include <math.h>

// ---------------- problem constants ----------------
#define S_TOK   1536
#define HID     2880
#define NH      64
#define NKV     8
#define DH      64
#define QKV_DIM 5120
#define QDIM    4096
#define KOFF    4096
#define VOFF    4608
#define SM_SCALE 0.125f

// ---------------- scratch ----------------
__device__ __half g_t_h[S_TOK * HID];       // rmsnorm out fp16
__device__ __half g_w1[QKV_DIM * HID];      // qkv_w fp16
__device__ __half g_w2[HID * QDIM];         // out_w fp16
__device__ __half g_qkvh[S_TOK * QKV_DIM];  // qkv fp16 (rope applied in place)
__device__ __half g_qlo[S_TOK * QDIM];      // q lo residual plane
__device__ __half g_o_h[S_TOK * QDIM];      // attention out fp16
__device__ float g_cos[S_TOK * 32];
__device__ float g_sin[S_TOK * 32];

// ---------------- helpers ----------------
__device__ __forceinline__ uint32_t smem_u32(const void* p) {
    uint32_t a;
    asm("{ .reg .u64 t; cvta.to.shared.u64 t, %1; cvt.u32.u64 %0, t; }" : "=r"(a) : "l"(p));
    return a;
}

__device__ __forceinline__ void ldsm4(uint32_t* r, uint32_t addr) {
    asm volatile("ldmatrix.sync.aligned.m8n8.x4.shared.b16 {%0,%1,%2,%3}, [%4];"
                 : "=r"(r[0]), "=r"(r[1]), "=r"(r[2]), "=r"(r[3]) : "r"(addr));
}

__device__ __forceinline__ void ldsm4t(uint32_t* r, uint32_t addr) {
    asm volatile("ldmatrix.sync.aligned.m8n8.x4.trans.shared.b16 {%0,%1,%2,%3}, [%4];"
                 : "=r"(r[0]), "=r"(r[1]), "=r"(r[2]), "=r"(r[3]) : "r"(addr));
}

__device__ __forceinline__ void mma_f16(float* c, const uint32_t* a, const uint32_t* b) {
    asm volatile("mma.sync.aligned.m16n8k16.row.col.f32.f16.f16.f32 "
                 "{%0,%1,%2,%3}, {%4,%5,%6,%7}, {%8,%9}, {%0,%1,%2,%3};"
                 : "+f"(c[0]), "+f"(c[1]), "+f"(c[2]), "+f"(c[3])
                 : "r"(a[0]), "r"(a[1]), "r"(a[2]), "r"(a[3]), "r"(b[0]), "r"(b[1]));
}

__device__ __forceinline__ uint32_t pack_h2(float a, float b) {
    __half2 h = __floats2half2_rn(a, b);
    return *(uint32_t*)&h;
}

// ============================================================
// 1) fused prelude: rmsnorm | rope tables | w1 convert | w2 convert
// ============================================================
#define NB_RMS 1536
#define NB_TAB 192
#define NB_W1  14400
#define NB_W2  11520
#define NB_TOTAL (NB_RMS + NB_TAB + NB_W1 + NB_W2)

__global__ void __launch_bounds__(256)
prelude_kernel(const float* __restrict__ x, const float* __restrict__ scale,
               const float4* __restrict__ w1src, const float4* __restrict__ w2src) {
    const int b = blockIdx.x;
    const int tid = threadIdx.x;
    __shared__ float red[8];

    if (b < NB_RMS) {
        int s = b;
        const float4* xr = (const float4*)(x + (size_t)s * HID);
        const float4* sc = (const float4*)scale;
        float ss = 0.f;
        for (int i = tid; i < HID / 4; i += 256) {
            float4 v = xr[i];
            ss += v.x * v.x + v.y * v.y + v.z * v.z + v.w * v.w;
        }
        for (int o = 16; o > 0; o >>= 1) ss += __shfl_xor_sync(0xffffffff, ss, o);
        int wid = tid >> 5, lid = tid & 31;
        if (lid == 0) red[wid] = ss;
        __syncthreads();
        if (wid == 0) {
            float v = (lid < 8) ? red[lid] : 0.f;
            for (int o = 4; o > 0; o >>= 1) v += __shfl_xor_sync(0xffffffff, v, o);
            if (lid == 0) red[0] = v;
        }
        __syncthreads();
        float r = rsqrtf(red[0] / (float)HID + 1e-5f);
        uint2* th = (uint2*)(g_t_h + (size_t)s * HID);
        for (int i = tid; i < HID / 4; i += 256) {
            float4 v = xr[i];
            float4 g = sc[i];
            uint2 hh;
            hh.x = pack_h2(v.x * r * g.x, v.y * r * g.y);
            hh.y = pack_h2(v.z * r * g.z, v.w * r * g.w);
            th[i] = hh;
        }
    } else if (b < NB_RMS + NB_TAB) {
        int gid = (b - NB_RMS) * 256 + tid;
        int s = gid >> 5;
        int i = gid & 31;
        const double TWO_PI = 6.283185307179586;
        double freq = pow(150000.0, (double)(2 * i) / 64.0);
        double conc = 0.1 * log(32.0) + 1.0;
        double lo = 32.0 * log(4096.0 / (32.0 * TWO_PI)) / log(150000.0);
        double hi = 32.0 * log(4096.0 / (1.0 * TWO_PI)) / log(150000.0);
        double interp = 1.0 / (32.0 * freq);
        double extrap = 1.0 / freq;
        double ramp = ((double)i - lo) / (hi - lo);
        double mask = 1.0 - fmin(fmax(ramp, 0.0), 1.0);
        double invf = interp * (1.0 - mask) + extrap * mask;
        double f = (double)s * invf;
        g_cos[gid] = (float)(cos(f) * conc);
        g_sin[gid] = (float)(sin(f) * conc);
    } else if (b < NB_RMS + NB_TAB + NB_W1) {
        int i = (b - NB_RMS - NB_TAB) * 256 + tid;
        float4 v = w1src[i];
        uint2 o;
        o.x = pack_h2(v.x, v.y);
        o.y = pack_h2(v.z, v.w);
        ((uint2*)g_w1)[i] = o;
    } else {
        int i = (b - NB_RMS - NB_TAB - NB_W1) * 256 + tid;
        float4 v = w2src[i];
        uint2 o;
        o.x = pack_h2(v.x, v.y);
        o.y = pack_h2(v.z, v.w);
        ((uint2*)g_w2)[i] = o;
    }
}

// ============================================================
// 2) mma.sync fp16 GEMM, templated on mode/tile:
//    MODE 0: C fp32 = A B^T + bias + resid (out proj)
//    MODE 1: qkv epilogue -> g_qkvh fp16 (+ g_qlo for q cols)
// ============================================================
template <int ROWS>
__device__ __forceinline__ void load_tile_256(uint32_t sbase, const __half* __restrict__ g,
                                              int row0, int nrows, int ldk, int k0, int tid) {
#pragma unroll
    for (int u = 0; u < ROWS * 8 / 256; u++) {
        int unit = u * 256 + tid;
        int r = unit >> 3;
        int c16 = unit & 7;
        uint32_t off = (uint32_t)(r * 128 + ((c16 * 16) ^ ((r & 7) << 4)));
        int gr = row0 + r;
        int ok = (gr < nrows) ? 16 : 0;
        const __half* src = g + (size_t)((gr < nrows) ? gr : 0) * ldk + k0 + c16 * 8;
        asm volatile("cp.async.cg.shared.global [%0], [%1], 16, %2;"
                     :: "r"(sbase + off), "l"(src), "r"(ok) : "memory");
    }
}

template <int MODE, int BMv, int BNv, int MINB>
__global__ void __launch_bounds__(256, MINB)
gemm_mma(const __half* __restrict__ A, const __half* __restrict__ B,
         const float* __restrict__ bias, const float* __restrict__ resid,
         float* __restrict__ Cf, int M, int N, int K) {
    constexpr int MT = BMv / 32;             // m16 frags per warp (wm dim = 2)
    constexpr int NT = BNv / 32;             // n8 frags per warp (wn dim = 4)
    constexpr int TILE_A = BMv * 128;
    constexpr int TILE_Bt = BNv * 128;
    constexpr int STAGE = TILE_A + TILE_Bt;
    extern __shared__ char smem_raw[];
    uint32_t sb = (smem_u32(smem_raw) + 1023u) & ~1023u;

    const int tid = threadIdx.x;
    const int wid = tid >> 5;
    const int lane = tid & 31;
    const int wm = wid & 1;
    const int wn = wid >> 1;
    const int bm = blockIdx.y * BMv;
    const int bn = blockIdx.x * BNv;

    float acc[MT][NT][4];
#pragma unroll
    for (int i = 0; i < MT; i++)
#pragma unroll
        for (int j = 0; j < NT; j++)
#pragma unroll
            for (int k = 0; k < 4; k++) acc[i][j][k] = 0.f;

    const int a_r = wm * (BMv / 2) + (lane & 15);
    const uint32_t a_cx = (uint32_t)((a_r & 7) << 4);
    const int b_r = wn * (BNv / 4) + ((lane >> 4) << 3) + (lane & 7);
    const uint32_t b_cx = (uint32_t)((b_r & 7) << 4);

    const int NC = K / 64;

#pragma unroll
    for (int c = 0; c < 2; c++) {
        uint32_t st = sb + c * STAGE;
        load_tile_256<BMv>(st, A, bm, M, K, c * 64, tid);
        load_tile_256<BNv>(st + TILE_A, B, bn, N, K, c * 64, tid);
        asm volatile("cp.async.commit_group;" ::: "memory");
    }

    for (int c = 0; c < NC; c++) {
        int pf = c + 2;
        if (pf < NC) {
            uint32_t st = sb + (pf % 3) * STAGE;
            load_tile_256<BMv>(st, A, bm, M, K, pf * 64, tid);
            load_tile_256<BNv>(st + TILE_A, B, bn, N, K, pf * 64, tid);
        }
        asm volatile("cp.async.commit_group;" ::: "memory");
        asm volatile("cp.async.wait_group 2;" ::: "memory");
        __syncthreads();

        const uint32_t st = sb + (c % 3) * STAGE;
#pragma unroll
        for (int ks = 0; ks < 4; ks++) {
            uint32_t ah[MT][4], bh[NT / 2][4];
            const uint32_t acb = (uint32_t)(ks * 32 + ((lane >> 4) << 4));
#pragma unroll
            for (int mt = 0; mt < MT; mt++) {
                uint32_t off = (uint32_t)((a_r + mt * 16) * 128) + (acb ^ a_cx);
                ldsm4(ah[mt], st + off);
            }
            const uint32_t bcb = (uint32_t)(ks * 32 + ((lane >> 3) & 1) * 16);
#pragma unroll
            for (int p = 0; p < NT / 2; p++) {
                uint32_t off = (uint32_t)((b_r + p * 16) * 128) + (bcb ^ b_cx);
                ldsm4(bh[p], st + TILE_A + off);
            }
#pragma unroll
            for (int mt = 0; mt < MT; mt++) {
#pragma unroll
                for (int nt = 0; nt < NT; nt++) {
                    mma_f16(acc[mt][nt], ah[mt], &bh[nt >> 1][(nt & 1) * 2]);
                }
            }
        }
        __syncthreads();
    }

    const int row0 = bm + wm * (BMv / 2);
    const int col0 = bn + wn * (BNv / 4);
#pragma unroll
    for (int mt = 0; mt < MT; mt++) {
#pragma unroll
        for (int nt = 0; nt < NT; nt++) {
            int r = row0 + mt * 16 + (lane >> 2);
            int c0 = col0 + nt * 8 + (lane & 3) * 2;
            if (c0 >= N) continue;
            float bx = bias[c0], by = bias[c0 + 1];
            float2 v0, v1;
            v0.x = acc[mt][nt][0] + bx; v0.y = acc[mt][nt][1] + by;
            v1.x = acc[mt][nt][2] + bx; v1.y = acc[mt][nt][3] + by;
            if (MODE == 0) {
                const float2 x0 = *(const float2*)(resid + (size_t)r * N + c0);
                const float2 x1 = *(const float2*)(resid + (size_t)(r + 8) * N + c0);
                v0.x += x0.x; v0.y += x0.y;
                v1.x += x1.x; v1.y += x1.y;
                *(float2*)(Cf + (size_t)r * N + c0) = v0;
                *(float2*)(Cf + (size_t)(r + 8) * N + c0) = v1;
            } else {
                __half2 h0 = __floats2half2_rn(v0.x, v0.y);
                __half2 h1 = __floats2half2_rn(v1.x, v1.y);
                *(__half2*)(g_qkvh + (size_t)r * QKV_DIM + c0) = h0;
                *(__half2*)(g_qkvh + (size_t)(r + 8) * QKV_DIM + c0) = h1;
                if (c0 < QDIM) {
                    __half2 l0 = __floats2half2_rn(v0.x - __half2float(h0.x),
                                                   v0.y - __half2float(h0.y));
                    __half2 l1 = __floats2half2_rn(v1.x - __half2float(h1.x),
                                                   v1.y - __half2float(h1.y));
                    *(__half2*)(g_qlo + (size_t)r * QDIM + c0) = l0;
                    *(__half2*)(g_qlo + (size_t)(r + 8) * QDIM + c0) = l1;
                }
            }
        }
    }
}

// ============================================================
// 3) prep: rope q (hi+lo recombined, re-split) and k, in place
// ============================================================
__global__ void __launch_bounds__(128)
prep_attn_kernel() {
    int s = blockIdx.x;
    int tid = threadIdx.x;
    __shared__ float cs[32], sn[32];
    if (tid < 32) { cs[tid] = g_cos[s * 32 + tid]; sn[tid] = g_sin[s * 32 + tid]; }
    __syncthreads();

    __half* qrow = g_qkvh + (size_t)s * QKV_DIM;
    __half* lrow = g_qlo + (size_t)s * QDIM;

    for (int i = tid; i < 2048; i += 128) {
        int hh = i >> 5, d = i & 31;
        int o = hh * 64 + d;
        float x1 = __half2float(qrow[o]) + __half2float(lrow[o]);
        float x2 = __half2float(qrow[o + 32]) + __half2float(lrow[o + 32]);
        float c = cs[d], ss = sn[d];
        float r1 = (x1 * c - x2 * ss) * SM_SCALE;
        float r2 = (x2 * c + x1 * ss) * SM_SCALE;
        __half h1 = __float2half_rn(r1), h2 = __float2half_rn(r2);
        qrow[o] = h1; qrow[o + 32] = h2;
        lrow[o]      = __float2half_rn(r1 - __half2float(h1));
        lrow[o + 32] = __float2half_rn(r2 - __half2float(h2));
    }
    for (int i = tid; i < 256; i += 128) {
        int kvh = i >> 5, d = i & 31;
        int o = KOFF + kvh * 64 + d;
        float x1 = __half2float(qrow[o]);
        float x2 = __half2float(qrow[o + 32]);
        float c = cs[d], ss = sn[d];
        qrow[o]      = __float2half_rn(x1 * c - x2 * ss);
        qrow[o + 32] = __float2half_rn(x2 * c + x1 * ss);
    }
}

// ============================================================
// 4) tensorized flash attention with sinks
// ============================================================
#define ATT_STAGE 16384
#define ATT_SMEM_TOTAL (1024 + 16384 + 2 * ATT_STAGE)

__device__ __forceinline__ void stage64(uint32_t sbase, const __half* __restrict__ g,
                                        int row_stride, int tid) {
#pragma unroll
    for (int u = 0; u < 4; u++) {
        int unit = u * 128 + tid;
        int r = unit >> 3, c16 = unit & 7;
        uint32_t off = (uint32_t)(r * 128 + ((c16 * 16) ^ ((r & 7) << 4)));
        const __half* src = g + (size_t)r * row_stride + c16 * 8;
        asm volatile("cp.async.cg.shared.global [%0], [%1], 16;"
                     :: "r"(sbase + off), "l"(src) : "memory");
    }
}

__device__ __forceinline__ void stage_kv(uint32_t base, int kt, int kv, int tid) {
    const __half* kr = g_qkvh + (size_t)(kt * 64) * QKV_DIM + KOFF + kv * 64;
    const __half* vr = g_qkvh + (size_t)(kt * 64) * QKV_DIM + VOFF + kv * 64;
    stage64(base,        kr, QKV_DIM, tid);
    stage64(base + 8192, vr, QKV_DIM, tid);
}

__global__ void __launch_bounds__(128)
attn_mma_kernel(const float* __restrict__ sinks) {
    extern __shared__ char sraw[];
    uint32_t sb = (smem_u32(sraw) + 1023u) & ~1023u;
    const uint32_t QHB = sb, QLB = sb + 8192, KVB = sb + 16384;

    const int qt = blockIdx.x, h = blockIdx.y, kv = h & 7;
    const int tid = threadIdx.x, w = tid >> 5, lane = tid & 31;

    stage64(QHB, g_qkvh + (size_t)(qt * 64) * QKV_DIM + h * 64, QKV_DIM, tid);
    stage64(QLB, g_qlo + (size_t)(qt * 64) * QDIM + h * 64, QDIM, tid);
    stage_kv(KVB, 0, kv, tid);
    asm volatile("cp.async.commit_group;" ::: "memory");
    asm volatile("cp.async.wait_group 0;" ::: "memory");
    __syncthreads();

    uint32_t qh[4][4], ql[4][4];
    {
        int a_r = w * 16 + (lane & 15);
        uint32_t ax = (uint32_t)((a_r & 7) << 4);
#pragma unroll
        for (int kt4 = 0; kt4 < 4; kt4++) {
            uint32_t cb = (uint32_t)(kt4 * 32 + ((lane >> 4) << 4));
            uint32_t off = (uint32_t)(a_r * 128) + (cb ^ ax);
            ldsm4(qh[kt4], QHB + off);
            ldsm4(ql[kt4], QLB + off);
        }
    }

    float O[8][4];
#pragma unroll
    for (int nt = 0; nt < 8; nt++)
#pragma unroll
        for (int j = 0; j < 4; j++) O[nt][j] = 0.f;

    float mA = sinks[h], mB = mA, lA = 1.f, lB = 1.f;
    const int q0 = qt * 64 + w * 16 + (lane >> 2);
    const int b_rbase = ((lane >> 4) << 3) + (lane & 7);
    const uint32_t bsel = (uint32_t)(((lane >> 3) & 1) * 16);
    const int v_rl = lane & 15;
    const uint32_t v_cb = (uint32_t)((lane >> 4) << 4);

    for (int kt = 0; kt <= qt; kt++) {
        if (kt + 1 <= qt)
            stage_kv(KVB + ((kt + 1) & 1) * ATT_STAGE, kt + 1, kv, tid);
        asm volatile("cp.async.commit_group;" ::: "memory");
        asm volatile("cp.async.wait_group 1;" ::: "memory");
        __syncthreads();

        const uint32_t kb = KVB + (kt & 1) * ATT_STAGE;
        const uint32_t vb = kb + 8192;

        float sc[8][4];
#pragma unroll
        for (int nt = 0; nt < 8; nt++)
#pragma unroll
            for (int j = 0; j < 4; j++) sc[nt][j] = 0.f;

#pragma unroll
        for (int kt4 = 0; kt4 < 4; kt4++) {
#pragma unroll
            for (int kg = 0; kg < 4; kg++) {
                int b_r = kg * 16 + b_rbase;
                uint32_t off = (uint32_t)(b_r * 128) + (((uint32_t)(kt4 * 32) + bsel) ^ ((uint32_t)((b_r & 7) << 4)));
                uint32_t bh4[4];
                ldsm4(bh4, kb + off);
#pragma unroll
                for (int n2 = 0; n2 < 2; n2++) {
                    float* s = sc[2 * kg + n2];
                    mma_f16(s, qh[kt4], &bh4[n2 * 2]);
                    mma_f16(s, ql[kt4], &bh4[n2 * 2]);
                }
            }
        }

        if (kt == qt) {
#pragma unroll
            for (int nt = 0; nt < 8; nt++) {
                int key = kt * 64 + nt * 8 + 2 * (lane & 3);
                if (key > q0)         sc[nt][0] = -1e30f;
                if (key + 1 > q0)     sc[nt][1] = -1e30f;
                if (key > q0 + 8)     sc[nt][2] = -1e30f;
                if (key + 1 > q0 + 8) sc[nt][3] = -1e30f;
            }
        }

        float r0 = -1e30f, r1 = -1e30f;
#pragma unroll
        for (int nt = 0; nt < 8; nt++) {
            r0 = fmaxf(r0, fmaxf(sc[nt][0], sc[nt][1]));
            r1 = fmaxf(r1, fmaxf(sc[nt][2], sc[nt][3]));
        }
        r0 = fmaxf(r0, __shfl_xor_sync(0xffffffffu, r0, 1));
        r0 = fmaxf(r0, __shfl_xor_sync(0xffffffffu, r0, 2));
        r1 = fmaxf(r1, __shfl_xor_sync(0xffffffffu, r1, 1));
        r1 = fmaxf(r1, __shfl_xor_sync(0xffffffffu, r1, 2));
        float mA2 = fmaxf(mA, r0), mB2 = fmaxf(mB, r1);
        float cA = __expf(mA - mA2), cB = __expf(mB - mB2);
        mA = mA2; mB = mB2;

        float sA = 0.f, sB = 0.f;
#pragma unroll
        for (int nt = 0; nt < 8; nt++) {
            sc[nt][0] = __expf(sc[nt][0] - mA);
            sc[nt][1] = __expf(sc[nt][1] - mA);
            sc[nt][2] = __expf(sc[nt][2] - mB);
            sc[nt][3] = __expf(sc[nt][3] - mB);
            sA += sc[nt][0] + sc[nt][1];
            sB += sc[nt][2] + sc[nt][3];
        }
        sA += __shfl_xor_sync(0xffffffffu, sA, 1);
        sA += __shfl_xor_sync(0xffffffffu, sA, 2);
        sB += __shfl_xor_sync(0xffffffffu, sB, 1);
        sB += __shfl_xor_sync(0xffffffffu, sB, 2);
        lA = lA * cA + sA;
        lB = lB * cB + sB;
#pragma unroll
        for (int nt = 0; nt < 8; nt++) {
            O[nt][0] *= cA; O[nt][1] *= cA;
            O[nt][2] *= cB; O[nt][3] *= cB;
        }

#pragma unroll
        for (int sg = 0; sg < 4; sg++) {
            uint32_t ph[4];
            ph[0] = pack_h2(sc[2 * sg][0], sc[2 * sg][1]);
            ph[1] = pack_h2(sc[2 * sg][2], sc[2 * sg][3]);
            ph[2] = pack_h2(sc[2 * sg + 1][0], sc[2 * sg + 1][1]);
            ph[3] = pack_h2(sc[2 * sg + 1][2], sc[2 * sg + 1][3]);
            int vrow = sg * 16 + v_rl;
            uint32_t rxor = (uint32_t)((vrow & 7) << 4);
#pragma unroll
            for (int dg = 0; dg < 4; dg++) {
                uint32_t off = (uint32_t)(vrow * 128) + (((uint32_t)(dg * 32) + v_cb) ^ rxor);
                uint32_t vt[4];
                ldsm4t(vt, vb + off);
                mma_f16(O[2 * dg + 0], ph, &vt[0]);
                mma_f16(O[2 * dg + 1], ph, &vt[2]);
            }
        }
        __syncthreads();
    }

    float iA = 1.f / lA, iB = 1.f / lB;
    size_t r0o = (size_t)q0 * QDIM + h * 64;
    size_t r1o = r0o + (size_t)8 * QDIM;
#pragma unroll
    for (int nt = 0; nt < 8; nt++) {
        int c = nt * 8 + 2 * (lane & 3);
        *(uint32_t*)(g_o_h + r0o + c) = pack_h2(O[nt][0] * iA, O[nt][1] * iA);
        *(uint32_t*)(g_o_h + r1o + c) = pack_h2(O[nt][2] * iB, O[nt][3] * iB);
    }
}

// ============================================================
// launch
// ============================================================
#define SMEM_G1 (3 * (128 * 128 + 256 * 128) + 1024)
#define SMEM_G0 (3 * (128 * 128 + 128 * 128) + 1024)

extern "C" void kernel_launch(void* const* d_in, const int* in_sizes, int n_in,
                              void* d_out, int out_size) {
    const float* x          = (const float*)d_in[0];
    const float* sinks      = (const float*)d_in[1];
    const float* norm_scale = (const float*)d_in[2];
    const float* qkv_w      = (const float*)d_in[3];
    const float* qkv_b      = (const float*)d_in[4];
    const float* out_w      = (const float*)d_in[5];
    const float* out_b      = (const float*)d_in[6];
    float* out = (float*)d_out;

    __half *th, *w1, *w2, *oh;
    cudaGetSymbolAddress((void**)&th, g_t_h);
    cudaGetSymbolAddress((void**)&w1, g_w1);
    cudaGetSymbolAddress((void**)&w2, g_w2);
    cudaGetSymbolAddress((void**)&oh, g_o_h);

    cudaFuncSetAttribute((const void*)gemm_mma<1, 128, 256, 1>,
                         cudaFuncAttributeMaxDynamicSharedMemorySize, SMEM_G1);
    cudaFuncSetAttribute((const void*)gemm_mma<0, 128, 128, 2>,
                         cudaFuncAttributeMaxDynamicSharedMemorySize, SMEM_G0);
    cudaFuncSetAttribute((const void*)attn_mma_kernel,
                         cudaFuncAttributeMaxDynamicSharedMemorySize, ATT_SMEM_TOTAL);

    // fused prelude: rmsnorm + rope tables + both weight converts
    prelude_kernel<<<NB_TOTAL, 256>>>(x, norm_scale,
                                      (const float4*)qkv_w, (const float4*)out_w);

    // qkv = t @ qkv_w^T + qkv_b -> fp16 qkv (+ q lo plane)   [128x256 tile]
    gemm_mma<1, 128, 256, 1><<<dim3(QKV_DIM / 256, S_TOK / 128), 256, SMEM_G1>>>(
        th, w1, qkv_b, nullptr, nullptr, S_TOK, QKV_DIM, HID);

    // rope q (2-term) + k, in place
    prep_attn_kernel<<<S_TOK, 128>>>();

    // tensorized attention
    attn_mma_kernel<<<dim3(S_TOK / 64, NH), 128, ATT_SMEM_TOTAL>>>(sinks);

    // y = o @ out_w^T + out_b + x   [128x128 tile]
    gemm_mma<0, 128, 128, 2><<<dim3((HID + 127) / 128, S_TOK / 128), 256, SMEM_G0>>>(
        oh, w2, out_b, x, out, S_TOK, HID, QDIM);
}

// round 8
// speedup vs baseline: 1.0184x; 1.0184x over previous
#include <cuda_runtime.h>
#include <cuda_fp16.h>
#include <cstdint>
#include <math.h>

// ---------------- problem constants ----------------
#define S_TOK   1536
#define HID     2880
#define NH      64
#define NKV     8
#define DH      64
#define QKV_DIM 5120
#define QDIM    4096
#define KOFF    4096
#define VOFF    4608
#define SM_SCALE 0.125f

// ---------------- scratch ----------------
__device__ __half g_t_h[S_TOK * HID];       // rmsnorm out fp16
__device__ __half g_w1[QKV_DIM * HID];      // qkv_w fp16
__device__ __half g_w2[HID * QDIM];         // out_w fp16
__device__ __half g_qkvh[S_TOK * QKV_DIM];  // qkv fp16 (rope applied in place)
__device__ __half g_qlo[S_TOK * QDIM];      // q lo residual plane
__device__ __half g_o_h[S_TOK * QDIM];      // attention out fp16
__device__ float g_cos[S_TOK * 32];
__device__ float g_sin[S_TOK * 32];

// ---------------- helpers ----------------
__device__ __forceinline__ uint32_t smem_u32(const void* p) {
    uint32_t a;
    asm("{ .reg .u64 t; cvta.to.shared.u64 t, %1; cvt.u32.u64 %0, t; }" : "=r"(a) : "l"(p));
    return a;
}

__device__ __forceinline__ void ldsm4(uint32_t* r, uint32_t addr) {
    asm volatile("ldmatrix.sync.aligned.m8n8.x4.shared.b16 {%0,%1,%2,%3}, [%4];"
                 : "=r"(r[0]), "=r"(r[1]), "=r"(r[2]), "=r"(r[3]) : "r"(addr));
}

__device__ __forceinline__ void ldsm4t(uint32_t* r, uint32_t addr) {
    asm volatile("ldmatrix.sync.aligned.m8n8.x4.trans.shared.b16 {%0,%1,%2,%3}, [%4];"
                 : "=r"(r[0]), "=r"(r[1]), "=r"(r[2]), "=r"(r[3]) : "r"(addr));
}

__device__ __forceinline__ void mma_f16(float* c, const uint32_t* a, const uint32_t* b) {
    asm volatile("mma.sync.aligned.m16n8k16.row.col.f32.f16.f16.f32 "
                 "{%0,%1,%2,%3}, {%4,%5,%6,%7}, {%8,%9}, {%0,%1,%2,%3};"
                 : "+f"(c[0]), "+f"(c[1]), "+f"(c[2]), "+f"(c[3])
                 : "r"(a[0]), "r"(a[1]), "r"(a[2]), "r"(a[3]), "r"(b[0]), "r"(b[1]));
}

__device__ __forceinline__ uint32_t pack_h2(float a, float b) {
    __half2 h = __floats2half2_rn(a, b);
    return *(uint32_t*)&h;
}

// ============================================================
// 1) fused prelude: rmsnorm | rope tables | w1 convert | w2 convert
// ============================================================
#define NB_RMS 1536
#define NB_TAB 192
#define NB_W1  14400
#define NB_W2  11520
#define NB_TOTAL (NB_RMS + NB_TAB + NB_W1 + NB_W2)

__global__ void __launch_bounds__(256)
prelude_kernel(const float* __restrict__ x, const float* __restrict__ scale,
               const float4* __restrict__ w1src, const float4* __restrict__ w2src) {
    const int b = blockIdx.x;
    const int tid = threadIdx.x;
    __shared__ float red[8];

    if (b < NB_RMS) {
        int s = b;
        const float4* xr = (const float4*)(x + (size_t)s * HID);
        const float4* sc = (const float4*)scale;
        float ss = 0.f;
        for (int i = tid; i < HID / 4; i += 256) {
            float4 v = xr[i];
            ss += v.x * v.x + v.y * v.y + v.z * v.z + v.w * v.w;
        }
        for (int o = 16; o > 0; o >>= 1) ss += __shfl_xor_sync(0xffffffff, ss, o);
        int wid = tid >> 5, lid = tid & 31;
        if (lid == 0) red[wid] = ss;
        __syncthreads();
        if (wid == 0) {
            float v = (lid < 8) ? red[lid] : 0.f;
            for (int o = 4; o > 0; o >>= 1) v += __shfl_xor_sync(0xffffffff, v, o);
            if (lid == 0) red[0] = v;
        }
        __syncthreads();
        float r = rsqrtf(red[0] / (float)HID + 1e-5f);
        uint2* th = (uint2*)(g_t_h + (size_t)s * HID);
        for (int i = tid; i < HID / 4; i += 256) {
            float4 v = xr[i];
            float4 g = sc[i];
            uint2 hh;
            hh.x = pack_h2(v.x * r * g.x, v.y * r * g.y);
            hh.y = pack_h2(v.z * r * g.z, v.w * r * g.w);
            th[i] = hh;
        }
    } else if (b < NB_RMS + NB_TAB) {
        int gid = (b - NB_RMS) * 256 + tid;
        int s = gid >> 5;
        int i = gid & 31;
        const double TWO_PI = 6.283185307179586;
        double freq = pow(150000.0, (double)(2 * i) / 64.0);
        double conc = 0.1 * log(32.0) + 1.0;
        double lo = 32.0 * log(4096.0 / (32.0 * TWO_PI)) / log(150000.0);
        double hi = 32.0 * log(4096.0 / (1.0 * TWO_PI)) / log(150000.0);
        double interp = 1.0 / (32.0 * freq);
        double extrap = 1.0 / freq;
        double ramp = ((double)i - lo) / (hi - lo);
        double mask = 1.0 - fmin(fmax(ramp, 0.0), 1.0);
        double invf = interp * (1.0 - mask) + extrap * mask;
        double f = (double)s * invf;
        g_cos[gid] = (float)(cos(f) * conc);
        g_sin[gid] = (float)(sin(f) * conc);
    } else if (b < NB_RMS + NB_TAB + NB_W1) {
        int i = (b - NB_RMS - NB_TAB) * 256 + tid;
        float4 v = w1src[i];
        uint2 o;
        o.x = pack_h2(v.x, v.y);
        o.y = pack_h2(v.z, v.w);
        ((uint2*)g_w1)[i] = o;
    } else {
        int i = (b - NB_RMS - NB_TAB - NB_W1) * 256 + tid;
        float4 v = w2src[i];
        uint2 o;
        o.x = pack_h2(v.x, v.y);
        o.y = pack_h2(v.z, v.w);
        ((uint2*)g_w2)[i] = o;
    }
}

// ============================================================
// 2) mma.sync fp16 GEMM 128x128x64, 256 threads, 2 CTAs/SM:
//    MODE 0: C fp32 = A B^T + bias + resid (out proj)
//    MODE 1: qkv epilogue -> g_qkvh fp16 (+ g_qlo for q cols)
// ============================================================
#define TILE_B 16384            // 128 rows x 128 bytes
#define STAGE_B (2 * TILE_B)
#define SMEM_GEMM (3 * STAGE_B + 1024)

__device__ __forceinline__ void load_tile_256(uint32_t sbase, const __half* __restrict__ g,
                                              int row0, int nrows, int ldk, int k0, int tid) {
#pragma unroll
    for (int u = 0; u < 4; u++) {
        int unit = u * 256 + tid;
        int r = unit >> 3;
        int c16 = unit & 7;
        uint32_t off = (uint32_t)(r * 128 + ((c16 * 16) ^ ((r & 7) << 4)));
        int gr = row0 + r;
        int ok = (gr < nrows) ? 16 : 0;
        const __half* src = g + (size_t)((gr < nrows) ? gr : 0) * ldk + k0 + c16 * 8;
        asm volatile("cp.async.cg.shared.global [%0], [%1], 16, %2;"
                     :: "r"(sbase + off), "l"(src), "r"(ok) : "memory");
    }
}

__device__ __forceinline__ void load_stage(uint32_t st,
                                           const __half* A, const __half* B,
                                           int bm, int bn, int M, int N, int K, int k0, int tid) {
    load_tile_256(st,          A, bm, M, K, k0, tid);
    load_tile_256(st + TILE_B, B, bn, N, K, k0, tid);
}

template <int MODE>
__global__ void __launch_bounds__(256, 2)
gemm_mma(const __half* __restrict__ A, const __half* __restrict__ B,
         const float* __restrict__ bias, const float* __restrict__ resid,
         float* __restrict__ Cf, int M, int N, int K) {
    extern __shared__ char smem_raw[];
    uint32_t sb = (smem_u32(smem_raw) + 1023u) & ~1023u;

    const int tid = threadIdx.x;
    const int wid = tid >> 5;
    const int lane = tid & 31;
    const int wm = wid & 1;
    const int wn = wid >> 1;
    const int bm = blockIdx.y * 128;
    const int bn = blockIdx.x * 128;

    float acc[4][4][4];
#pragma unroll
    for (int i = 0; i < 4; i++)
#pragma unroll
        for (int j = 0; j < 4; j++)
#pragma unroll
            for (int k = 0; k < 4; k++) acc[i][j][k] = 0.f;

    const int a_r = wm * 64 + (lane & 15);
    const uint32_t a_cx = (uint32_t)((a_r & 7) << 4);
    const int b_r = wn * 32 + ((lane >> 4) << 3) + (lane & 7);
    const uint32_t b_cx = (uint32_t)((b_r & 7) << 4);

    const int NC = K / 64;

#pragma unroll
    for (int c = 0; c < 2; c++) {
        load_stage(sb + c * STAGE_B, A, B, bm, bn, M, N, K, c * 64, tid);
        asm volatile("cp.async.commit_group;" ::: "memory");
    }

    for (int c = 0; c < NC; c++) {
        int pf = c + 2;
        if (pf < NC) {
            load_stage(sb + (pf % 3) * STAGE_B, A, B, bm, bn, M, N, K, pf * 64, tid);
        }
        asm volatile("cp.async.commit_group;" ::: "memory");
        asm volatile("cp.async.wait_group 2;" ::: "memory");
        __syncthreads();

        const uint32_t st = sb + (c % 3) * STAGE_B;
#pragma unroll
        for (int ks = 0; ks < 4; ks++) {
            uint32_t ah[4][4], bh[2][4];
            const uint32_t acb = (uint32_t)(ks * 32 + ((lane >> 4) << 4));
#pragma unroll
            for (int mt = 0; mt < 4; mt++) {
                uint32_t off = (uint32_t)((a_r + mt * 16) * 128) + (acb ^ a_cx);
                ldsm4(ah[mt], st + off);
            }
            const uint32_t bcb = (uint32_t)(ks * 32 + ((lane >> 3) & 1) * 16);
#pragma unroll
            for (int p = 0; p < 2; p++) {
                uint32_t off = (uint32_t)((b_r + p * 16) * 128) + (bcb ^ b_cx);
                ldsm4(bh[p], st + TILE_B + off);
            }
#pragma unroll
            for (int mt = 0; mt < 4; mt++) {
#pragma unroll
                for (int nt = 0; nt < 4; nt++) {
                    mma_f16(acc[mt][nt], ah[mt], &bh[nt >> 1][(nt & 1) * 2]);
                }
            }
        }
        __syncthreads();
    }

    const int row0 = bm + wm * 64;
    const int col0 = bn + wn * 32;
#pragma unroll
    for (int mt = 0; mt < 4; mt++) {
#pragma unroll
        for (int nt = 0; nt < 4; nt++) {
            int r = row0 + mt * 16 + (lane >> 2);
            int c0 = col0 + nt * 8 + (lane & 3) * 2;
            if (c0 >= N) continue;
            float bx = bias[c0], by = bias[c0 + 1];
            float2 v0, v1;
            v0.x = acc[mt][nt][0] + bx; v0.y = acc[mt][nt][1] + by;
            v1.x = acc[mt][nt][2] + bx; v1.y = acc[mt][nt][3] + by;
            if (MODE == 0) {
                const float2 x0 = *(const float2*)(resid + (size_t)r * N + c0);
                const float2 x1 = *(const float2*)(resid + (size_t)(r + 8) * N + c0);
                v0.x += x0.x; v0.y += x0.y;
                v1.x += x1.x; v1.y += x1.y;
                *(float2*)(Cf + (size_t)r * N + c0) = v0;
                *(float2*)(Cf + (size_t)(r + 8) * N + c0) = v1;
            } else {
                __half2 h0 = __floats2half2_rn(v0.x, v0.y);
                __half2 h1 = __floats2half2_rn(v1.x, v1.y);
                *(__half2*)(g_qkvh + (size_t)r * QKV_DIM + c0) = h0;
                *(__half2*)(g_qkvh + (size_t)(r + 8) * QKV_DIM + c0) = h1;
                if (c0 < QDIM) {
                    __half2 l0 = __floats2half2_rn(v0.x - __half2float(h0.x),
                                                   v0.y - __half2float(h0.y));
                    __half2 l1 = __floats2half2_rn(v1.x - __half2float(h1.x),
                                                   v1.y - __half2float(h1.y));
                    *(__half2*)(g_qlo + (size_t)r * QDIM + c0) = l0;
                    *(__half2*)(g_qlo + (size_t)(r + 8) * QDIM + c0) = l1;
                }
            }
        }
    }
}

// ============================================================
// 3) prep: rope q (hi+lo recombined, re-split) and k, in place
// ============================================================
__global__ void __launch_bounds__(128)
prep_attn_kernel() {
    int s = blockIdx.x;
    int tid = threadIdx.x;
    __shared__ float cs[32], sn[32];
    if (tid < 32) { cs[tid] = g_cos[s * 32 + tid]; sn[tid] = g_sin[s * 32 + tid]; }
    __syncthreads();

    __half* qrow = g_qkvh + (size_t)s * QKV_DIM;
    __half* lrow = g_qlo + (size_t)s * QDIM;

    for (int i = tid; i < 2048; i += 128) {
        int hh = i >> 5, d = i & 31;
        int o = hh * 64 + d;
        float x1 = __half2float(qrow[o]) + __half2float(lrow[o]);
        float x2 = __half2float(qrow[o + 32]) + __half2float(lrow[o + 32]);
        float c = cs[d], ss = sn[d];
        float r1 = (x1 * c - x2 * ss) * SM_SCALE;
        float r2 = (x2 * c + x1 * ss) * SM_SCALE;
        __half h1 = __float2half_rn(r1), h2 = __float2half_rn(r2);
        qrow[o] = h1; qrow[o + 32] = h2;
        lrow[o]      = __float2half_rn(r1 - __half2float(h1));
        lrow[o + 32] = __float2half_rn(r2 - __half2float(h2));
    }
    for (int i = tid; i < 256; i += 128) {
        int kvh = i >> 5, d = i & 31;
        int o = KOFF + kvh * 64 + d;
        float x1 = __half2float(qrow[o]);
        float x2 = __half2float(qrow[o + 32]);
        float c = cs[d], ss = sn[d];
        qrow[o]      = __float2half_rn(x1 * c - x2 * ss);
        qrow[o + 32] = __float2half_rn(x2 * c + x1 * ss);
    }
}

// ============================================================
// 4) tensorized flash attention with sinks (long blocks first)
// ============================================================
#define ATT_STAGE 16384
#define ATT_SMEM_TOTAL (1024 + 16384 + 2 * ATT_STAGE)

__device__ __forceinline__ void stage64(uint32_t sbase, const __half* __restrict__ g,
                                        int row_stride, int tid) {
#pragma unroll
    for (int u = 0; u < 4; u++) {
        int unit = u * 128 + tid;
        int r = unit >> 3, c16 = unit & 7;
        uint32_t off = (uint32_t)(r * 128 + ((c16 * 16) ^ ((r & 7) << 4)));
        const __half* src = g + (size_t)r * row_stride + c16 * 8;
        asm volatile("cp.async.cg.shared.global [%0], [%1], 16;"
                     :: "r"(sbase + off), "l"(src) : "memory");
    }
}

__device__ __forceinline__ void stage_kv(uint32_t base, int kt, int kv, int tid) {
    const __half* kr = g_qkvh + (size_t)(kt * 64) * QKV_DIM + KOFF + kv * 64;
    const __half* vr = g_qkvh + (size_t)(kt * 64) * QKV_DIM + VOFF + kv * 64;
    stage64(base,        kr, QKV_DIM, tid);
    stage64(base + 8192, vr, QKV_DIM, tid);
}

__global__ void __launch_bounds__(128)
attn_mma_kernel(const float* __restrict__ sinks) {
    extern __shared__ char sraw[];
    uint32_t sb = (smem_u32(sraw) + 1023u) & ~1023u;
    const uint32_t QHB = sb, QLB = sb + 8192, KVB = sb + 16384;

    const int qt = (int)gridDim.x - 1 - (int)blockIdx.x;   // long blocks first
    const int h = blockIdx.y, kv = h & 7;
    const int tid = threadIdx.x, w = tid >> 5, lane = tid & 31;

    stage64(QHB, g_qkvh + (size_t)(qt * 64) * QKV_DIM + h * 64, QKV_DIM, tid);
    stage64(QLB, g_qlo + (size_t)(qt * 64) * QDIM + h * 64, QDIM, tid);
    stage_kv(KVB, 0, kv, tid);
    asm volatile("cp.async.commit_group;" ::: "memory");
    asm volatile("cp.async.wait_group 0;" ::: "memory");
    __syncthreads();

    uint32_t qh[4][4], ql[4][4];
    {
        int a_r = w * 16 + (lane & 15);
        uint32_t ax = (uint32_t)((a_r & 7) << 4);
#pragma unroll
        for (int kt4 = 0; kt4 < 4; kt4++) {
            uint32_t cb = (uint32_t)(kt4 * 32 + ((lane >> 4) << 4));
            uint32_t off = (uint32_t)(a_r * 128) + (cb ^ ax);
            ldsm4(qh[kt4], QHB + off);
            ldsm4(ql[kt4], QLB + off);
        }
    }

    float O[8][4];
#pragma unroll
    for (int nt = 0; nt < 8; nt++)
#pragma unroll
        for (int j = 0; j < 4; j++) O[nt][j] = 0.f;

    float mA = sinks[h], mB = mA, lA = 1.f, lB = 1.f;
    const int q0 = qt * 64 + w * 16 + (lane >> 2);
    const int b_rbase = ((lane >> 4) << 3) + (lane & 7);
    const uint32_t bsel = (uint32_t)(((lane >> 3) & 1) * 16);
    const int v_rl = lane & 15;
    const uint32_t v_cb = (uint32_t)((lane >> 4) << 4);

    for (int kt = 0; kt <= qt; kt++) {
        if (kt + 1 <= qt)
            stage_kv(KVB + ((kt + 1) & 1) * ATT_STAGE, kt + 1, kv, tid);
        asm volatile("cp.async.commit_group;" ::: "memory");
        asm volatile("cp.async.wait_group 1;" ::: "memory");
        __syncthreads();

        const uint32_t kb = KVB + (kt & 1) * ATT_STAGE;
        const uint32_t vb = kb + 8192;

        float sc[8][4];
#pragma unroll
        for (int nt = 0; nt < 8; nt++)
#pragma unroll
            for (int j = 0; j < 4; j++) sc[nt][j] = 0.f;

#pragma unroll
        for (int kt4 = 0; kt4 < 4; kt4++) {
#pragma unroll
            for (int kg = 0; kg < 4; kg++) {
                int b_r = kg * 16 + b_rbase;
                uint32_t off = (uint32_t)(b_r * 128) + (((uint32_t)(kt4 * 32) + bsel) ^ ((uint32_t)((b_r & 7) << 4)));
                uint32_t bh4[4];
                ldsm4(bh4, kb + off);
#pragma unroll
                for (int n2 = 0; n2 < 2; n2++) {
                    float* s = sc[2 * kg + n2];
                    mma_f16(s, qh[kt4], &bh4[n2 * 2]);
                    mma_f16(s, ql[kt4], &bh4[n2 * 2]);
                }
            }
        }

        if (kt == qt) {
#pragma unroll
            for (int nt = 0; nt < 8; nt++) {
                int key = kt * 64 + nt * 8 + 2 * (lane & 3);
                if (key > q0)         sc[nt][0] = -1e30f;
                if (key + 1 > q0)     sc[nt][1] = -1e30f;
                if (key > q0 + 8)     sc[nt][2] = -1e30f;
                if (key + 1 > q0 + 8) sc[nt][3] = -1e30f;
            }
        }

        float r0 = -1e30f, r1 = -1e30f;
#pragma unroll
        for (int nt = 0; nt < 8; nt++) {
            r0 = fmaxf(r0, fmaxf(sc[nt][0], sc[nt][1]));
            r1 = fmaxf(r1, fmaxf(sc[nt][2], sc[nt][3]));
        }
        r0 = fmaxf(r0, __shfl_xor_sync(0xffffffffu, r0, 1));
        r0 = fmaxf(r0, __shfl_xor_sync(0xffffffffu, r0, 2));
        r1 = fmaxf(r1, __shfl_xor_sync(0xffffffffu, r1, 1));
        r1 = fmaxf(r1, __shfl_xor_sync(0xffffffffu, r1, 2));
        float mA2 = fmaxf(mA, r0), mB2 = fmaxf(mB, r1);
        float cA = __expf(mA - mA2), cB = __expf(mB - mB2);
        mA = mA2; mB = mB2;

        float sA = 0.f, sB = 0.f;
#pragma unroll
        for (int nt = 0; nt < 8; nt++) {
            sc[nt][0] = __expf(sc[nt][0] - mA);
            sc[nt][1] = __expf(sc[nt][1] - mA);
            sc[nt][2] = __expf(sc[nt][2] - mB);
            sc[nt][3] = __expf(sc[nt][3] - mB);
            sA += sc[nt][0] + sc[nt][1];
            sB += sc[nt][2] + sc[nt][3];
        }
        sA += __shfl_xor_sync(0xffffffffu, sA, 1);
        sA += __shfl_xor_sync(0xffffffffu, sA, 2);
        sB += __shfl_xor_sync(0xffffffffu, sB, 1);
        sB += __shfl_xor_sync(0xffffffffu, sB, 2);
        lA = lA * cA + sA;
        lB = lB * cB + sB;
#pragma unroll
        for (int nt = 0; nt < 8; nt++) {
            O[nt][0] *= cA; O[nt][1] *= cA;
            O[nt][2] *= cB; O[nt][3] *= cB;
        }

#pragma unroll
        for (int sg = 0; sg < 4; sg++) {
            uint32_t ph[4];
            ph[0] = pack_h2(sc[2 * sg][0], sc[2 * sg][1]);
            ph[1] = pack_h2(sc[2 * sg][2], sc[2 * sg][3]);
            ph[2] = pack_h2(sc[2 * sg + 1][0], sc[2 * sg + 1][1]);
            ph[3] = pack_h2(sc[2 * sg + 1][2], sc[2 * sg + 1][3]);
            int vrow = sg * 16 + v_rl;
            uint32_t rxor = (uint32_t)((vrow & 7) << 4);
#pragma unroll
            for (int dg = 0; dg < 4; dg++) {
                uint32_t off = (uint32_t)(vrow * 128) + (((uint32_t)(dg * 32) + v_cb) ^ rxor);
                uint32_t vt[4];
                ldsm4t(vt, vb + off);
                mma_f16(O[2 * dg + 0], ph, &vt[0]);
                mma_f16(O[2 * dg + 1], ph, &vt[2]);
            }
        }
        __syncthreads();
    }

    float iA = 1.f / lA, iB = 1.f / lB;
    size_t r0o = (size_t)q0 * QDIM + h * 64;
    size_t r1o = r0o + (size_t)8 * QDIM;
#pragma unroll
    for (int nt = 0; nt < 8; nt++) {
        int c = nt * 8 + 2 * (lane & 3);
        *(uint32_t*)(g_o_h + r0o + c) = pack_h2(O[nt][0] * iA, O[nt][1] * iA);
        *(uint32_t*)(g_o_h + r1o + c) = pack_h2(O[nt][2] * iB, O[nt][3] * iB);
    }
}

// ============================================================
// launch
// ============================================================
extern "C" void kernel_launch(void* const* d_in, const int* in_sizes, int n_in,
                              void* d_out, int out_size) {
    const float* x          = (const float*)d_in[0];
    const float* sinks      = (const float*)d_in[1];
    const float* norm_scale = (const float*)d_in[2];
    const float* qkv_w      = (const float*)d_in[3];
    const float* qkv_b      = (const float*)d_in[4];
    const float* out_w      = (const float*)d_in[5];
    const float* out_b      = (const float*)d_in[6];
    float* out = (float*)d_out;

    __half *th, *w1, *w2, *oh;
    cudaGetSymbolAddress((void**)&th, g_t_h);
    cudaGetSymbolAddress((void**)&w1, g_w1);
    cudaGetSymbolAddress((void**)&w2, g_w2);
    cudaGetSymbolAddress((void**)&oh, g_o_h);

    cudaFuncSetAttribute((const void*)gemm_mma<1>,
                         cudaFuncAttributeMaxDynamicSharedMemorySize, SMEM_GEMM);
    cudaFuncSetAttribute((const void*)gemm_mma<0>,
                         cudaFuncAttributeMaxDynamicSharedMemorySize, SMEM_GEMM);
    cudaFuncSetAttribute((const void*)attn_mma_kernel,
                         cudaFuncAttributeMaxDynamicSharedMemorySize, ATT_SMEM_TOTAL);

    // fused prelude: rmsnorm + rope tables + both weight converts
    prelude_kernel<<<NB_TOTAL, 256>>>(x, norm_scale,
                                      (const float4*)qkv_w, (const float4*)out_w);

    // qkv = t @ qkv_w^T + qkv_b -> fp16 qkv (+ q lo plane)   [128x128, 2 CTA/SM]
    gemm_mma<1><<<dim3(QKV_DIM / 128, S_TOK / 128), 256, SMEM_GEMM>>>(
        th, w1, qkv_b, nullptr, nullptr, S_TOK, QKV_DIM, HID);

    // rope q (2-term) + k, in place
    prep_attn_kernel<<<S_TOK, 128>>>();

    // tensorized attention (long blocks scheduled first)
    attn_mma_kernel<<<dim3(S_TOK / 64, NH), 128, ATT_SMEM_TOTAL>>>(sinks);

    // y = o @ out_w^T + out_b + x   [128x128, 2 CTA/SM]
    gemm_mma<0><<<dim3((HID + 127) / 128, S_TOK / 128), 256, SMEM_GEMM>>>(
        oh, w2, out_b, x, out, S_TOK, HID, QDIM);
}

// round 9
// speedup vs baseline: 1.1375x; 1.1170x over previous
#include <cuda_runtime.h>
#include <cuda_fp16.h>
#include <cstdint>
#include <math.h>

// ---------------- problem constants ----------------
#define S_TOK   1536
#define HID     2880
#define NH      64
#define NKV     8
#define DH      64
#define QKV_DIM 5120
#define QDIM    4096
#define KOFF    4096
#define VOFF    4608
#define SM_SCALE 0.125f

// ---------------- scratch ----------------
__device__ float g_qkv[S_TOK * QKV_DIM];
__device__ __half g_t_h[S_TOK * HID];
__device__ __half g_w1[QKV_DIM * HID];
__device__ __half g_w2[HID * QDIM];
__device__ __half g_q_h[S_TOK * QDIM];
__device__ __half g_q_l[S_TOK * QDIM];
__device__ __half g_k_h[NKV * S_TOK * DH];
__device__ __half g_vt_h[NKV * DH * S_TOK];
__device__ __half g_o_h[S_TOK * QDIM];
__device__ float g_cos[S_TOK * 32];
__device__ float g_sin[S_TOK * 32];

// ---------------- helpers ----------------
__device__ __forceinline__ uint32_t smem_u32(const void* p) {
    uint32_t a;
    asm("{ .reg .u64 t; cvta.to.shared.u64 t, %1; cvt.u32.u64 %0, t; }" : "=r"(a) : "l"(p));
    return a;
}

__device__ __forceinline__ void ldsm4(uint32_t* r, uint32_t addr) {
    asm volatile("ldmatrix.sync.aligned.m8n8.x4.shared.b16 {%0,%1,%2,%3}, [%4];"
                 : "=r"(r[0]), "=r"(r[1]), "=r"(r[2]), "=r"(r[3]) : "r"(addr));
}

__device__ __forceinline__ void mma_f16(float* c, const uint32_t* a, const uint32_t* b) {
    asm volatile("mma.sync.aligned.m16n8k16.row.col.f32.f16.f16.f32 "
                 "{%0,%1,%2,%3}, {%4,%5,%6,%7}, {%8,%9}, {%0,%1,%2,%3};"
                 : "+f"(c[0]), "+f"(c[1]), "+f"(c[2]), "+f"(c[3])
                 : "r"(a[0]), "r"(a[1]), "r"(a[2]), "r"(a[3]), "r"(b[0]), "r"(b[1]));
}

__device__ __forceinline__ uint32_t pack_h2(float a, float b) {
    __half2 h = __floats2half2_rn(a, b);
    return *(uint32_t*)&h;
}

// ============================================================
// 1) RMSNorm -> fp16 (hi only)
// ============================================================
__global__ void rmsnorm_kernel(const float* __restrict__ x,
                               const float* __restrict__ scale) {
    int s = blockIdx.x;
    const float4* xr = (const float4*)(x + (size_t)s * HID);
    const float4* sc = (const float4*)scale;

    float ss = 0.f;
    for (int i = threadIdx.x; i < HID / 4; i += blockDim.x) {
        float4 v = xr[i];
        ss += v.x * v.x + v.y * v.y + v.z * v.z + v.w * v.w;
    }
    for (int o = 16; o > 0; o >>= 1) ss += __shfl_xor_sync(0xffffffff, ss, o);
    __shared__ float red[8];
    int wid = threadIdx.x >> 5, lid = threadIdx.x & 31;
    if (lid == 0) red[wid] = ss;
    __syncthreads();
    if (wid == 0) {
        float v = (lid < (blockDim.x >> 5)) ? red[lid] : 0.f;
        for (int o = 4; o > 0; o >>= 1) v += __shfl_xor_sync(0xffffffff, v, o);
        if (lid == 0) red[0] = v;
    }
    __syncthreads();
    float r = rsqrtf(red[0] / (float)HID + 1e-5f);

    uint2* th = (uint2*)(g_t_h + (size_t)s * HID);
    for (int i = threadIdx.x; i < HID / 4; i += blockDim.x) {
        float4 v = xr[i];
        float4 g = sc[i];
        uint2 hh;
        hh.x = pack_h2(v.x * r * g.x, v.y * r * g.y);
        hh.y = pack_h2(v.z * r * g.z, v.w * r * g.w);
        th[i] = hh;
    }
}

// ============================================================
// 2) fp32 -> fp16 convert (weights)
// ============================================================
__global__ void convert_h_kernel(const float4* __restrict__ src,
                                 uint2* __restrict__ dst, int n4) {
    int i = blockIdx.x * blockDim.x + threadIdx.x;
    if (i >= n4) return;
    float4 v = src[i];
    uint2 o;
    o.x = pack_h2(v.x, v.y);
    o.y = pack_h2(v.z, v.w);
    dst[i] = o;
}

// ============================================================
// 3) mma.sync fp16 GEMM: C = A B^T + bias (+resid)
//    CTA 128x128x64, 256 threads, warp tile 64x32
// ============================================================
#define BM 128
#define BN 128
#define BK 64
#define TILE_B 16384            // 128 rows x 128 bytes
#define STAGE_B (2 * TILE_B)    // A, B
#define GEMM_STAGES 3
#define SMEM_TOTAL_GEMM (GEMM_STAGES * STAGE_B + 1024)

__device__ __forceinline__ void load_tile_256(uint32_t sbase, const __half* __restrict__ g,
                                              int row0, int nrows, int ldk, int k0, int tid) {
#pragma unroll
    for (int u = 0; u < 4; u++) {
        int unit = u * 256 + tid;
        int r = unit >> 3;
        int c16 = unit & 7;
        uint32_t off = (uint32_t)(r * 128 + ((c16 * 16) ^ ((r & 7) << 4)));
        int gr = row0 + r;
        int ok = (gr < nrows) ? 16 : 0;
        const __half* src = g + (size_t)((gr < nrows) ? gr : 0) * ldk + k0 + c16 * 8;
        asm volatile("cp.async.cg.shared.global [%0], [%1], 16, %2;"
                     :: "r"(sbase + off), "l"(src), "r"(ok) : "memory");
    }
}

__device__ __forceinline__ void load_stage(uint32_t st,
                                           const __half* A, const __half* B,
                                           int bm, int bn, int M, int N, int K, int k0, int tid) {
    load_tile_256(st,          A, bm, M, K, k0, tid);
    load_tile_256(st + TILE_B, B, bn, N, K, k0, tid);
}

template <bool RESID>
__global__ void __launch_bounds__(256, 2)
gemm_mma(const __half* __restrict__ A, const __half* __restrict__ B,
         const float* __restrict__ bias, const float* __restrict__ resid,
         float* __restrict__ C, int M, int N, int K) {
    extern __shared__ char smem_raw[];
    uint32_t sb = (smem_u32(smem_raw) + 1023u) & ~1023u;

    const int tid = threadIdx.x;
    const int wid = tid >> 5;
    const int lane = tid & 31;
    const int wm = wid & 1;
    const int wn = wid >> 1;
    const int bm = blockIdx.y * BM;
    const int bn = blockIdx.x * BN;

    float acc[4][4][4];
#pragma unroll
    for (int i = 0; i < 4; i++)
#pragma unroll
        for (int j = 0; j < 4; j++)
#pragma unroll
            for (int k = 0; k < 4; k++) acc[i][j][k] = 0.f;

    const int a_r = wm * 64 + (lane & 15);
    const uint32_t a_cx = (uint32_t)((a_r & 7) << 4);
    const int b_r = wn * 32 + ((lane >> 4) << 3) + (lane & 7);
    const uint32_t b_cx = (uint32_t)((b_r & 7) << 4);

    const int NC = K / BK;

#pragma unroll
    for (int c = 0; c < 2; c++) {
        load_stage(sb + c * STAGE_B, A, B, bm, bn, M, N, K, c * BK, tid);
        asm volatile("cp.async.commit_group;" ::: "memory");
    }

    for (int c = 0; c < NC; c++) {
        int pf = c + 2;
        if (pf < NC) {
            load_stage(sb + (pf % GEMM_STAGES) * STAGE_B, A, B, bm, bn, M, N, K, pf * BK, tid);
        }
        asm volatile("cp.async.commit_group;" ::: "memory");
        asm volatile("cp.async.wait_group 2;" ::: "memory");
        __syncthreads();

        const uint32_t st = sb + (c % GEMM_STAGES) * STAGE_B;
#pragma unroll
        for (int ks = 0; ks < 4; ks++) {
            uint32_t ah[4][4], bh[2][4];
            const uint32_t acb = (uint32_t)(ks * 32 + ((lane >> 4) << 4));
#pragma unroll
            for (int mt = 0; mt < 4; mt++) {
                uint32_t off = (uint32_t)((a_r + mt * 16) * 128) + (acb ^ a_cx);
                ldsm4(ah[mt], st + off);
            }
            const uint32_t bcb = (uint32_t)(ks * 32 + ((lane >> 3) & 1) * 16);
#pragma unroll
            for (int p = 0; p < 2; p++) {
                uint32_t off = (uint32_t)((b_r + p * 16) * 128) + (bcb ^ b_cx);
                ldsm4(bh[p], st + TILE_B + off);
            }
#pragma unroll
            for (int mt = 0; mt < 4; mt++) {
#pragma unroll
                for (int nt = 0; nt < 4; nt++) {
                    mma_f16(acc[mt][nt], ah[mt], &bh[nt >> 1][(nt & 1) * 2]);
                }
            }
        }
        __syncthreads();
    }

    const int row0 = bm + wm * 64;
    const int col0 = bn + wn * 32;
#pragma unroll
    for (int mt = 0; mt < 4; mt++) {
#pragma unroll
        for (int nt = 0; nt < 4; nt++) {
            int r = row0 + mt * 16 + (lane >> 2);
            int c0 = col0 + nt * 8 + (lane & 3) * 2;
            if (c0 < N) {
                float bx = bias[c0], by = bias[c0 + 1];
                float2 v0, v1;
                v0.x = acc[mt][nt][0] + bx; v0.y = acc[mt][nt][1] + by;
                v1.x = acc[mt][nt][2] + bx; v1.y = acc[mt][nt][3] + by;
                if (RESID) {
                    const float2 x0 = *(const float2*)(resid + (size_t)r * N + c0);
                    const float2 x1 = *(const float2*)(resid + (size_t)(r + 8) * N + c0);
                    v0.x += x0.x; v0.y += x0.y;
                    v1.x += x1.x; v1.y += x1.y;
                }
                *(float2*)(C + (size_t)r * N + c0) = v0;
                *(float2*)(C + (size_t)(r + 8) * N + c0) = v1;
            }
        }
    }
}

// ============================================================
// 4) YaRN RoPE tables (fp64, matches reference)
// ============================================================
__global__ void rope_tables_kernel() {
    int gid = blockIdx.x * blockDim.x + threadIdx.x;
    if (gid >= S_TOK * 32) return;
    int s = gid >> 5;
    int i = gid & 31;
    const double TWO_PI = 6.283185307179586;
    double freq = pow(150000.0, (double)(2 * i) / 64.0);
    double conc = 0.1 * log(32.0) + 1.0;
    double lo = 32.0 * log(4096.0 / (32.0 * TWO_PI)) / log(150000.0);
    double hi = 32.0 * log(4096.0 / (1.0 * TWO_PI)) / log(150000.0);
    double interp = 1.0 / (32.0 * freq);
    double extrap = 1.0 / freq;
    double ramp = ((double)i - lo) / (hi - lo);
    double mask = 1.0 - fmin(fmax(ramp, 0.0), 1.0);
    double invf = interp * (1.0 - mask) + extrap * mask;
    double f = (double)s * invf;
    g_cos[gid] = (float)(cos(f) * conc);
    g_sin[gid] = (float)(sin(f) * conc);
}

// ============================================================
// 5) prep: rope + scale; q hi/lo, k hi, v hi transposed
// ============================================================
__global__ void __launch_bounds__(128)
prep_attn_kernel() {
    int s = blockIdx.x;
    int tid = threadIdx.x;
    __shared__ float cs[32], sn[32];
    if (tid < 32) { cs[tid] = g_cos[s * 32 + tid]; sn[tid] = g_sin[s * 32 + tid]; }
    __syncthreads();
    const float* row = g_qkv + (size_t)s * QKV_DIM;

    // q: 64 heads x 32 rotation pairs, scaled, hi/lo
    for (int i = tid; i < 2048; i += 128) {
        int hh = i >> 5, d = i & 31;
        float x1 = row[hh * 64 + d], x2 = row[hh * 64 + 32 + d];
        float c = cs[d], ss = sn[d];
        float r1 = (x1 * c - x2 * ss) * SM_SCALE;
        float r2 = (x2 * c + x1 * ss) * SM_SCALE;
        size_t o = (size_t)s * QDIM + hh * 64 + d;
        __half h1 = __float2half_rn(r1), h2 = __float2half_rn(r2);
        g_q_h[o] = h1; g_q_h[o + 32] = h2;
        g_q_l[o] = __float2half_rn(r1 - __half2float(h1));
        g_q_l[o + 32] = __float2half_rn(r2 - __half2float(h2));
    }
    // k: 8 kv heads x 32 pairs, layout [kv][s][64], hi only
    for (int i = tid; i < 256; i += 128) {
        int kvh = i >> 5, d = i & 31;
        float x1 = row[KOFF + kvh * 64 + d], x2 = row[KOFF + kvh * 64 + 32 + d];
        float c = cs[d], ss = sn[d];
        size_t o = (size_t)kvh * S_TOK * DH + (size_t)s * DH + d;
        g_k_h[o]      = __float2half_rn(x1 * c - x2 * ss);
        g_k_h[o + 32] = __float2half_rn(x2 * c + x1 * ss);
    }
    // v: transpose -> [kv][d][s], hi only
    for (int i = tid; i < 512; i += 128) {
        int kvh = i >> 6, d = i & 63;
        float v = row[VOFF + kvh * 64 + d];
        g_vt_h[(size_t)kvh * DH * S_TOK + (size_t)d * S_TOK + s] = __float2half_rn(v);
    }
}

// ============================================================
// 6) tensorized flash attention with sinks
//    block: 64 q rows x 1 head, 4 warps (16 rows each)
// ============================================================
#define ATT_STAGE 16384         // kh 8KB + vh 8KB
#define ATT_SMEM_TOTAL (1024 + 16384 + 2 * ATT_STAGE)

__device__ __forceinline__ void stage64(uint32_t sbase, const __half* __restrict__ g,
                                        int row_stride, int tid) {
#pragma unroll
    for (int u = 0; u < 4; u++) {
        int unit = u * 128 + tid;
        int r = unit >> 3, c16 = unit & 7;
        uint32_t off = (uint32_t)(r * 128 + ((c16 * 16) ^ ((r & 7) << 4)));
        const __half* src = g + (size_t)r * row_stride + c16 * 8;
        asm volatile("cp.async.cg.shared.global [%0], [%1], 16;"
                     :: "r"(sbase + off), "l"(src) : "memory");
    }
}

__device__ __forceinline__ void stage_kv(uint32_t base, int kt, int kv, int tid) {
    const __half* kh = g_k_h + (size_t)kv * S_TOK * DH + (size_t)kt * 64 * DH;
    const __half* vh = g_vt_h + (size_t)kv * DH * S_TOK + kt * 64;
    stage64(base,        kh, DH, tid);
    stage64(base + 8192, vh, S_TOK, tid);
}

__global__ void __launch_bounds__(128)
attn_mma_kernel(const float* __restrict__ sinks) {
    extern __shared__ char sraw[];
    uint32_t sb = (smem_u32(sraw) + 1023u) & ~1023u;
    const uint32_t QHB = sb, QLB = sb + 8192, KVB = sb + 16384;

    const int qt = (int)gridDim.x - 1 - (int)blockIdx.x;   // long blocks first
    const int h = blockIdx.y, kv = h & 7;
    const int tid = threadIdx.x, w = tid >> 5, lane = tid & 31;

    stage64(QHB, g_q_h + (size_t)(qt * 64) * QDIM + h * 64, QDIM, tid);
    stage64(QLB, g_q_l + (size_t)(qt * 64) * QDIM + h * 64, QDIM, tid);
    stage_kv(KVB, 0, kv, tid);
    asm volatile("cp.async.commit_group;" ::: "memory");
    asm volatile("cp.async.wait_group 0;" ::: "memory");
    __syncthreads();

    uint32_t qh[4][4], ql[4][4];
    {
        int a_r = w * 16 + (lane & 15);
        uint32_t ax = (uint32_t)((a_r & 7) << 4);
#pragma unroll
        for (int kt4 = 0; kt4 < 4; kt4++) {
            uint32_t cb = (uint32_t)(kt4 * 32 + ((lane >> 4) << 4));
            uint32_t off = (uint32_t)(a_r * 128) + (cb ^ ax);
            ldsm4(qh[kt4], QHB + off);
            ldsm4(ql[kt4], QLB + off);
        }
    }

    float O[8][4];
#pragma unroll
    for (int nt = 0; nt < 8; nt++)
#pragma unroll
        for (int j = 0; j < 4; j++) O[nt][j] = 0.f;

    float mA = sinks[h], mB = mA, lA = 1.f, lB = 1.f;
    const int q0 = qt * 64 + w * 16 + (lane >> 2);
    const int b_rbase = ((lane >> 4) << 3) + (lane & 7);
    const uint32_t bsel = (uint32_t)(((lane >> 3) & 1) * 16);

    for (int kt = 0; kt <= qt; kt++) {
        if (kt + 1 <= qt)
            stage_kv(KVB + ((kt + 1) & 1) * ATT_STAGE, kt + 1, kv, tid);
        asm volatile("cp.async.commit_group;" ::: "memory");
        asm volatile("cp.async.wait_group 1;" ::: "memory");
        __syncthreads();

        const uint32_t kb = KVB + (kt & 1) * ATT_STAGE;
        const uint32_t vb = kb + 8192;

        float sc[8][4];
#pragma unroll
        for (int nt = 0; nt < 8; nt++)
#pragma unroll
            for (int j = 0; j < 4; j++) sc[nt][j] = 0.f;

#pragma unroll
        for (int kt4 = 0; kt4 < 4; kt4++) {
#pragma unroll
            for (int kg = 0; kg < 4; kg++) {
                int b_r = kg * 16 + b_rbase;
                uint32_t off = (uint32_t)(b_r * 128) + (((uint32_t)(kt4 * 32) + bsel) ^ ((uint32_t)((b_r & 7) << 4)));
                uint32_t bh4[4];
                ldsm4(bh4, kb + off);
#pragma unroll
                for (int n2 = 0; n2 < 2; n2++) {
                    float* s = sc[2 * kg + n2];
                    mma_f16(s, qh[kt4], &bh4[n2 * 2]);
                    mma_f16(s, ql[kt4], &bh4[n2 * 2]);
                }
            }
        }

        if (kt == qt) {
#pragma unroll
            for (int nt = 0; nt < 8; nt++) {
                int key = kt * 64 + nt * 8 + 2 * (lane & 3);
                if (key > q0)         sc[nt][0] = -1e30f;
                if (key + 1 > q0)     sc[nt][1] = -1e30f;
                if (key > q0 + 8)     sc[nt][2] = -1e30f;
                if (key + 1 > q0 + 8) sc[nt][3] = -1e30f;
            }
        }

        float r0 = -1e30f, r1 = -1e30f;
#pragma unroll
        for (int nt = 0; nt < 8; nt++) {
            r0 = fmaxf(r0, fmaxf(sc[nt][0], sc[nt][1]));
            r1 = fmaxf(r1, fmaxf(sc[nt][2], sc[nt][3]));
        }
        r0 = fmaxf(r0, __shfl_xor_sync(0xffffffffu, r0, 1));
        r0 = fmaxf(r0, __shfl_xor_sync(0xffffffffu, r0, 2));
        r1 = fmaxf(r1, __shfl_xor_sync(0xffffffffu, r1, 1));
        r1 = fmaxf(r1, __shfl_xor_sync(0xffffffffu, r1, 2));
        float mA2 = fmaxf(mA, r0), mB2 = fmaxf(mB, r1);
        float cA = __expf(mA - mA2), cB = __expf(mB - mB2);
        mA = mA2; mB = mB2;

        float sA = 0.f, sB = 0.f;
#pragma unroll
        for (int nt = 0; nt < 8; nt++) {
            sc[nt][0] = __expf(sc[nt][0] - mA);
            sc[nt][1] = __expf(sc[nt][1] - mA);
            sc[nt][2] = __expf(sc[nt][2] - mB);
            sc[nt][3] = __expf(sc[nt][3] - mB);
            sA += sc[nt][0] + sc[nt][1];
            sB += sc[nt][2] + sc[nt][3];
        }
        sA += __shfl_xor_sync(0xffffffffu, sA, 1);
        sA += __shfl_xor_sync(0xffffffffu, sA, 2);
        sB += __shfl_xor_sync(0xffffffffu, sB, 1);
        sB += __shfl_xor_sync(0xffffffffu, sB, 2);
        lA = lA * cA + sA;
        lB = lB * cB + sB;
#pragma unroll
        for (int nt = 0; nt < 8; nt++) {
            O[nt][0] *= cA; O[nt][1] *= cA;
            O[nt][2] *= cB; O[nt][3] *= cB;
        }

        // PV: p hi only, v hi only (vt layout [d][s], non-trans ldsm)
#pragma unroll
        for (int sg = 0; sg < 4; sg++) {
            uint32_t ph[4];
            ph[0] = pack_h2(sc[2 * sg][0], sc[2 * sg][1]);
            ph[1] = pack_h2(sc[2 * sg][2], sc[2 * sg][3]);
            ph[2] = pack_h2(sc[2 * sg + 1][0], sc[2 * sg + 1][1]);
            ph[3] = pack_h2(sc[2 * sg + 1][2], sc[2 * sg + 1][3]);
#pragma unroll
            for (int dg = 0; dg < 4; dg++) {
                int b_r = dg * 16 + b_rbase;
                uint32_t off = (uint32_t)(b_r * 128) + (((uint32_t)(sg * 32) + bsel) ^ ((uint32_t)((b_r & 7) << 4)));
                uint32_t vh4[4];
                ldsm4(vh4, vb + off);
#pragma unroll
                for (int n2 = 0; n2 < 2; n2++) {
                    mma_f16(O[2 * dg + n2], ph, &vh4[n2 * 2]);
                }
            }
        }
        __syncthreads();
    }

    // epilogue: o hi fp16
    float iA = 1.f / lA, iB = 1.f / lB;
    size_t r0o = (size_t)q0 * QDIM + h * 64;
    size_t r1o = r0o + (size_t)8 * QDIM;
#pragma unroll
    for (int nt = 0; nt < 8; nt++) {
        int c = nt * 8 + 2 * (lane & 3);
        *(uint32_t*)(g_o_h + r0o + c) = pack_h2(O[nt][0] * iA, O[nt][1] * iA);
        *(uint32_t*)(g_o_h + r1o + c) = pack_h2(O[nt][2] * iB, O[nt][3] * iB);
    }
}

// ============================================================
// launch
// ============================================================
extern "C" void kernel_launch(void* const* d_in, const int* in_sizes, int n_in,
                              void* d_out, int out_size) {
    const float* x          = (const float*)d_in[0];
    const float* sinks      = (const float*)d_in[1];
    const float* norm_scale = (const float*)d_in[2];
    const float* qkv_w      = (const float*)d_in[3];
    const float* qkv_b      = (const float*)d_in[4];
    const float* out_w      = (const float*)d_in[5];
    const float* out_b      = (const float*)d_in[6];
    float* out = (float*)d_out;

    float* g_qkv_p; cudaGetSymbolAddress((void**)&g_qkv_p, g_qkv);
    __half *th, *w1, *w2, *oh;
    cudaGetSymbolAddress((void**)&th, g_t_h);
    cudaGetSymbolAddress((void**)&w1, g_w1);
    cudaGetSymbolAddress((void**)&w2, g_w2);
    cudaGetSymbolAddress((void**)&oh, g_o_h);

    cudaFuncSetAttribute(gemm_mma<false>, cudaFuncAttributeMaxDynamicSharedMemorySize, SMEM_TOTAL_GEMM);
    cudaFuncSetAttribute(gemm_mma<true>,  cudaFuncAttributeMaxDynamicSharedMemorySize, SMEM_TOTAL_GEMM);
    cudaFuncSetAttribute(attn_mma_kernel, cudaFuncAttributeMaxDynamicSharedMemorySize, ATT_SMEM_TOTAL);

    rope_tables_kernel<<<(S_TOK * 32 + 255) / 256, 256>>>();
    {
        int n4 = QKV_DIM * HID / 4;
        convert_h_kernel<<<(n4 + 255) / 256, 256>>>((const float4*)qkv_w, (uint2*)w1, n4);
    }
    {
        int n4 = HID * QDIM / 4;
        convert_h_kernel<<<(n4 + 255) / 256, 256>>>((const float4*)out_w, (uint2*)w2, n4);
    }

    rmsnorm_kernel<<<S_TOK, 256>>>(x, norm_scale);

    // qkv = t @ qkv_w^T + qkv_b   (M=1536, N=5120, K=2880)
    gemm_mma<false><<<dim3(QKV_DIM / BN, S_TOK / BM), 256, SMEM_TOTAL_GEMM>>>(
        th, w1, qkv_b, nullptr, g_qkv_p, S_TOK, QKV_DIM, HID);

    // rope + split + v transpose
    prep_attn_kernel<<<S_TOK, 128>>>();

    // tensorized attention
    attn_mma_kernel<<<dim3(S_TOK / 64, NH), 128, ATT_SMEM_TOTAL>>>(sinks);

    // y = o @ out_w^T + out_b + x   (M=1536, N=2880, K=4096)
    gemm_mma<true><<<dim3((HID + BN - 1) / BN, S_TOK / BM), 256, SMEM_TOTAL_GEMM>>>(
        oh, w2, out_b, x, out, S_TOK, HID, QDIM);
}

// round 10
// speedup vs baseline: 1.1554x; 1.0157x over previous
#include <cuda_runtime.h>
#include <cuda_fp16.h>
#include <cstdint>
#include <math.h>

// ---------------- problem constants ----------------
#define S_TOK   1536
#define HID     2880
#define NH      64
#define NKV     8
#define DH      64
#define QKV_DIM 5120
#define QDIM    4096
#define KOFF    4096
#define VOFF    4608
#define SM_SCALE 0.125f

// ---------------- scratch ----------------
__device__ float g_qkv[S_TOK * QKV_DIM];
__device__ __half g_t_h[S_TOK * HID];
__device__ __half g_w1[QKV_DIM * HID];
__device__ __half g_w2[HID * QDIM];
__device__ __half g_q_h[S_TOK * QDIM];
__device__ __half g_q_l[S_TOK * QDIM];
__device__ __half g_k_h[NKV * S_TOK * DH];
__device__ __half g_vt_h[NKV * DH * S_TOK];
__device__ __half g_o_h[S_TOK * QDIM];
__device__ float g_cos[S_TOK * 32];
__device__ float g_sin[S_TOK * 32];

// ---------------- helpers ----------------
__device__ __forceinline__ uint32_t smem_u32(const void* p) {
    uint32_t a;
    asm("{ .reg .u64 t; cvta.to.shared.u64 t, %1; cvt.u32.u64 %0, t; }" : "=r"(a) : "l"(p));
    return a;
}

__device__ __forceinline__ void ldsm4(uint32_t* r, uint32_t addr) {
    asm volatile("ldmatrix.sync.aligned.m8n8.x4.shared.b16 {%0,%1,%2,%3}, [%4];"
                 : "=r"(r[0]), "=r"(r[1]), "=r"(r[2]), "=r"(r[3]) : "r"(addr));
}

__device__ __forceinline__ void mma_f16(float* c, const uint32_t* a, const uint32_t* b) {
    asm volatile("mma.sync.aligned.m16n8k16.row.col.f32.f16.f16.f32 "
                 "{%0,%1,%2,%3}, {%4,%5,%6,%7}, {%8,%9}, {%0,%1,%2,%3};"
                 : "+f"(c[0]), "+f"(c[1]), "+f"(c[2]), "+f"(c[3])
                 : "r"(a[0]), "r"(a[1]), "r"(a[2]), "r"(a[3]), "r"(b[0]), "r"(b[1]));
}

__device__ __forceinline__ uint32_t pack_h2(float a, float b) {
    __half2 h = __floats2half2_rn(a, b);
    return *(uint32_t*)&h;
}

// ============================================================
// 1) RMSNorm -> fp16 (hi only)
// ============================================================
__global__ void rmsnorm_kernel(const float* __restrict__ x,
                               const float* __restrict__ scale) {
    int s = blockIdx.x;
    const float4* xr = (const float4*)(x + (size_t)s * HID);
    const float4* sc = (const float4*)scale;

    float ss = 0.f;
    for (int i = threadIdx.x; i < HID / 4; i += blockDim.x) {
        float4 v = xr[i];
        ss += v.x * v.x + v.y * v.y + v.z * v.z + v.w * v.w;
    }
    for (int o = 16; o > 0; o >>= 1) ss += __shfl_xor_sync(0xffffffff, ss, o);
    __shared__ float red[8];
    int wid = threadIdx.x >> 5, lid = threadIdx.x & 31;
    if (lid == 0) red[wid] = ss;
    __syncthreads();
    if (wid == 0) {
        float v = (lid < (blockDim.x >> 5)) ? red[lid] : 0.f;
        for (int o = 4; o > 0; o >>= 1) v += __shfl_xor_sync(0xffffffff, v, o);
        if (lid == 0) red[0] = v;
    }
    __syncthreads();
    float r = rsqrtf(red[0] / (float)HID + 1e-5f);

    uint2* th = (uint2*)(g_t_h + (size_t)s * HID);
    for (int i = threadIdx.x; i < HID / 4; i += blockDim.x) {
        float4 v = xr[i];
        float4 g = sc[i];
        uint2 hh;
        hh.x = pack_h2(v.x * r * g.x, v.y * r * g.y);
        hh.y = pack_h2(v.z * r * g.z, v.w * r * g.w);
        th[i] = hh;
    }
}

// ============================================================
// 2) fp32 -> fp16 convert (weights)
// ============================================================
__global__ void convert_h_kernel(const float4* __restrict__ src,
                                 uint2* __restrict__ dst, int n4) {
    int i = blockIdx.x * blockDim.x + threadIdx.x;
    if (i >= n4) return;
    float4 v = src[i];
    uint2 o;
    o.x = pack_h2(v.x, v.y);
    o.y = pack_h2(v.z, v.w);
    dst[i] = o;
}

// ============================================================
// 3) mma.sync fp16 GEMM: C = A B^T + bias (+resid)
//    CTA 128x128x64, 128 threads (2x2 warps, warp tile 64x64)
// ============================================================
#define BM 128
#define BN 128
#define BK 64
#define TILE_B 16384            // 128 rows x 128 bytes
#define STAGE_B (2 * TILE_B)    // A, B
#define GEMM_STAGES 3
#define SMEM_TOTAL_GEMM (GEMM_STAGES * STAGE_B + 1024)

__device__ __forceinline__ void load_tile_128(uint32_t sbase, const __half* __restrict__ g,
                                              int row0, int nrows, int ldk, int k0, int tid) {
#pragma unroll
    for (int u = 0; u < 8; u++) {
        int unit = u * 128 + tid;       // 0..1023
        int r = unit >> 3;
        int c16 = unit & 7;
        uint32_t off = (uint32_t)(r * 128 + ((c16 * 16) ^ ((r & 7) << 4)));
        int gr = row0 + r;
        int ok = (gr < nrows) ? 16 : 0;
        const __half* src = g + (size_t)((gr < nrows) ? gr : 0) * ldk + k0 + c16 * 8;
        asm volatile("cp.async.cg.shared.global [%0], [%1], 16, %2;"
                     :: "r"(sbase + off), "l"(src), "r"(ok) : "memory");
    }
}

__device__ __forceinline__ void load_stage(uint32_t st,
                                           const __half* A, const __half* B,
                                           int bm, int bn, int M, int N, int K, int k0, int tid) {
    load_tile_128(st,          A, bm, M, K, k0, tid);
    load_tile_128(st + TILE_B, B, bn, N, K, k0, tid);
}

template <bool RESID>
__global__ void __launch_bounds__(128, 2)
gemm_mma(const __half* __restrict__ A, const __half* __restrict__ B,
         const float* __restrict__ bias, const float* __restrict__ resid,
         float* __restrict__ C, int M, int N, int K) {
    extern __shared__ char smem_raw[];
    uint32_t sb = (smem_u32(smem_raw) + 1023u) & ~1023u;

    const int tid = threadIdx.x;
    const int wid = tid >> 5;
    const int lane = tid & 31;
    const int wm = wid & 1;        // 0..1
    const int wn = wid >> 1;       // 0..1
    const int bm = blockIdx.y * BM;
    const int bn = blockIdx.x * BN;

    float acc[4][8][4];
#pragma unroll
    for (int i = 0; i < 4; i++)
#pragma unroll
        for (int j = 0; j < 8; j++)
#pragma unroll
            for (int k = 0; k < 4; k++) acc[i][j][k] = 0.f;

    const int a_r = wm * 64 + (lane & 15);
    const uint32_t a_cx = (uint32_t)((a_r & 7) << 4);
    const int b_r = wn * 64 + ((lane >> 4) << 3) + (lane & 7);
    const uint32_t b_cx = (uint32_t)((b_r & 7) << 4);

    const int NC = K / BK;

#pragma unroll
    for (int c = 0; c < 2; c++) {
        load_stage(sb + c * STAGE_B, A, B, bm, bn, M, N, K, c * BK, tid);
        asm volatile("cp.async.commit_group;" ::: "memory");
    }

    for (int c = 0; c < NC; c++) {
        int pf = c + 2;
        if (pf < NC) {
            load_stage(sb + (pf % GEMM_STAGES) * STAGE_B, A, B, bm, bn, M, N, K, pf * BK, tid);
        }
        asm volatile("cp.async.commit_group;" ::: "memory");
        asm volatile("cp.async.wait_group 2;" ::: "memory");
        __syncthreads();

        const uint32_t st = sb + (c % GEMM_STAGES) * STAGE_B;
#pragma unroll
        for (int ks = 0; ks < 4; ks++) {
            uint32_t ah[4][4], bh[4][4];
            const uint32_t acb = (uint32_t)(ks * 32 + ((lane >> 4) << 4));
#pragma unroll
            for (int mt = 0; mt < 4; mt++) {
                uint32_t off = (uint32_t)((a_r + mt * 16) * 128) + (acb ^ a_cx);
                ldsm4(ah[mt], st + off);
            }
            const uint32_t bcb = (uint32_t)(ks * 32 + ((lane >> 3) & 1) * 16);
#pragma unroll
            for (int p = 0; p < 4; p++) {
                uint32_t off = (uint32_t)((b_r + p * 16) * 128) + (bcb ^ b_cx);
                ldsm4(bh[p], st + TILE_B + off);
            }
#pragma unroll
            for (int mt = 0; mt < 4; mt++) {
#pragma unroll
                for (int nt = 0; nt < 8; nt++) {
                    mma_f16(acc[mt][nt], ah[mt], &bh[nt >> 1][(nt & 1) * 2]);
                }
            }
        }
        __syncthreads();
    }

    const int row0 = bm + wm * 64;
    const int col0 = bn + wn * 64;
#pragma unroll
    for (int mt = 0; mt < 4; mt++) {
#pragma unroll
        for (int nt = 0; nt < 8; nt++) {
            int r = row0 + mt * 16 + (lane >> 2);
            int c0 = col0 + nt * 8 + (lane & 3) * 2;
            if (c0 < N) {
                float bx = bias[c0], by = bias[c0 + 1];
                float2 v0, v1;
                v0.x = acc[mt][nt][0] + bx; v0.y = acc[mt][nt][1] + by;
                v1.x = acc[mt][nt][2] + bx; v1.y = acc[mt][nt][3] + by;
                if (RESID) {
                    const float2 x0 = *(const float2*)(resid + (size_t)r * N + c0);
                    const float2 x1 = *(const float2*)(resid + (size_t)(r + 8) * N + c0);
                    v0.x += x0.x; v0.y += x0.y;
                    v1.x += x1.x; v1.y += x1.y;
                }
                *(float2*)(C + (size_t)r * N + c0) = v0;
                *(float2*)(C + (size_t)(r + 8) * N + c0) = v1;
            }
        }
    }
}

// ============================================================
// 4) YaRN RoPE tables (fp64, matches reference)
// ============================================================
__global__ void rope_tables_kernel() {
    int gid = blockIdx.x * blockDim.x + threadIdx.x;
    if (gid >= S_TOK * 32) return;
    int s = gid >> 5;
    int i = gid & 31;
    const double TWO_PI = 6.283185307179586;
    double freq = pow(150000.0, (double)(2 * i) / 64.0);
    double conc = 0.1 * log(32.0) + 1.0;
    double lo = 32.0 * log(4096.0 / (32.0 * TWO_PI)) / log(150000.0);
    double hi = 32.0 * log(4096.0 / (1.0 * TWO_PI)) / log(150000.0);
    double interp = 1.0 / (32.0 * freq);
    double extrap = 1.0 / freq;
    double ramp = ((double)i - lo) / (hi - lo);
    double mask = 1.0 - fmin(fmax(ramp, 0.0), 1.0);
    double invf = interp * (1.0 - mask) + extrap * mask;
    double f = (double)s * invf;
    g_cos[gid] = (float)(cos(f) * conc);
    g_sin[gid] = (float)(sin(f) * conc);
}

// ============================================================
// 5) prep: rope + scale; q hi/lo, k hi, v hi transposed
// ============================================================
__global__ void __launch_bounds__(128)
prep_attn_kernel() {
    int s = blockIdx.x;
    int tid = threadIdx.x;
    __shared__ float cs[32], sn[32];
    if (tid < 32) { cs[tid] = g_cos[s * 32 + tid]; sn[tid] = g_sin[s * 32 + tid]; }
    __syncthreads();
    const float* row = g_qkv + (size_t)s * QKV_DIM;

    // q: 64 heads x 32 rotation pairs, scaled, hi/lo
    for (int i = tid; i < 2048; i += 128) {
        int hh = i >> 5, d = i & 31;
        float x1 = row[hh * 64 + d], x2 = row[hh * 64 + 32 + d];
        float c = cs[d], ss = sn[d];
        float r1 = (x1 * c - x2 * ss) * SM_SCALE;
        float r2 = (x2 * c + x1 * ss) * SM_SCALE;
        size_t o = (size_t)s * QDIM + hh * 64 + d;
        __half h1 = __float2half_rn(r1), h2 = __float2half_rn(r2);
        g_q_h[o] = h1; g_q_h[o + 32] = h2;
        g_q_l[o] = __float2half_rn(r1 - __half2float(h1));
        g_q_l[o + 32] = __float2half_rn(r2 - __half2float(h2));
    }
    // k: 8 kv heads x 32 pairs, layout [kv][s][64], hi only
    for (int i = tid; i < 256; i += 128) {
        int kvh = i >> 5, d = i & 31;
        float x1 = row[KOFF + kvh * 64 + d], x2 = row[KOFF + kvh * 64 + 32 + d];
        float c = cs[d], ss = sn[d];
        size_t o = (size_t)kvh * S_TOK * DH + (size_t)s * DH + d;
        g_k_h[o]      = __float2half_rn(x1 * c - x2 * ss);
        g_k_h[o + 32] = __float2half_rn(x2 * c + x1 * ss);
    }
    // v: transpose -> [kv][d][s], hi only
    for (int i = tid; i < 512; i += 128) {
        int kvh = i >> 6, d = i & 63;
        float v = row[VOFF + kvh * 64 + d];
        g_vt_h[(size_t)kvh * DH * S_TOK + (size_t)d * S_TOK + s] = __float2half_rn(v);
    }
}

// ============================================================
// 6) tensorized flash attention with sinks
//    block: 64 q rows x 1 head, 4 warps (16 rows each)
// ============================================================
#define ATT_STAGE 16384         // kh 8KB + vh 8KB
#define ATT_SMEM_TOTAL (1024 + 16384 + 2 * ATT_STAGE)

__device__ __forceinline__ void stage64(uint32_t sbase, const __half* __restrict__ g,
                                        int row_stride, int tid) {
#pragma unroll
    for (int u = 0; u < 4; u++) {
        int unit = u * 128 + tid;
        int r = unit >> 3, c16 = unit & 7;
        uint32_t off = (uint32_t)(r * 128 + ((c16 * 16) ^ ((r & 7) << 4)));
        const __half* src = g + (size_t)r * row_stride + c16 * 8;
        asm volatile("cp.async.cg.shared.global [%0], [%1], 16;"
                     :: "r"(sbase + off), "l"(src) : "memory");
    }
}

__device__ __forceinline__ void stage_kv(uint32_t base, int kt, int kv, int tid) {
    const __half* kh = g_k_h + (size_t)kv * S_TOK * DH + (size_t)kt * 64 * DH;
    const __half* vh = g_vt_h + (size_t)kv * DH * S_TOK + kt * 64;
    stage64(base,        kh, DH, tid);
    stage64(base + 8192, vh, S_TOK, tid);
}

__global__ void __launch_bounds__(128)
attn_mma_kernel(const float* __restrict__ sinks) {
    extern __shared__ char sraw[];
    uint32_t sb = (smem_u32(sraw) + 1023u) & ~1023u;
    const uint32_t QHB = sb, QLB = sb + 8192, KVB = sb + 16384;

    const int qt = (int)gridDim.x - 1 - (int)blockIdx.x;   // long blocks first
    const int h = blockIdx.y, kv = h & 7;
    const int tid = threadIdx.x, w = tid >> 5, lane = tid & 31;

    stage64(QHB, g_q_h + (size_t)(qt * 64) * QDIM + h * 64, QDIM, tid);
    stage64(QLB, g_q_l + (size_t)(qt * 64) * QDIM + h * 64, QDIM, tid);
    stage_kv(KVB, 0, kv, tid);
    asm volatile("cp.async.commit_group;" ::: "memory");
    asm volatile("cp.async.wait_group 0;" ::: "memory");
    __syncthreads();

    uint32_t qh[4][4], ql[4][4];
    {
        int a_r = w * 16 + (lane & 15);
        uint32_t ax = (uint32_t)((a_r & 7) << 4);
#pragma unroll
        for (int kt4 = 0; kt4 < 4; kt4++) {
            uint32_t cb = (uint32_t)(kt4 * 32 + ((lane >> 4) << 4));
            uint32_t off = (uint32_t)(a_r * 128) + (cb ^ ax);
            ldsm4(qh[kt4], QHB + off);
            ldsm4(ql[kt4], QLB + off);
        }
    }

    float O[8][4];
#pragma unroll
    for (int nt = 0; nt < 8; nt++)
#pragma unroll
        for (int j = 0; j < 4; j++) O[nt][j] = 0.f;

    float mA = sinks[h], mB = mA, lA = 1.f, lB = 1.f;
    const int q0 = qt * 64 + w * 16 + (lane >> 2);
    const int b_rbase = ((lane >> 4) << 3) + (lane & 7);
    const uint32_t bsel = (uint32_t)(((lane >> 3) & 1) * 16);

    for (int kt = 0; kt <= qt; kt++) {
        if (kt + 1 <= qt)
            stage_kv(KVB + ((kt + 1) & 1) * ATT_STAGE, kt + 1, kv, tid);
        asm volatile("cp.async.commit_group;" ::: "memory");
        asm volatile("cp.async.wait_group 1;" ::: "memory");
        __syncthreads();

        const uint32_t kb = KVB + (kt & 1) * ATT_STAGE;
        const uint32_t vb = kb + 8192;

        float sc[8][4];
#pragma unroll
        for (int nt = 0; nt < 8; nt++)
#pragma unroll
            for (int j = 0; j < 4; j++) sc[nt][j] = 0.f;

#pragma unroll
        for (int kt4 = 0; kt4 < 4; kt4++) {
#pragma unroll
            for (int kg = 0; kg < 4; kg++) {
                int b_r = kg * 16 + b_rbase;
                uint32_t off = (uint32_t)(b_r * 128) + (((uint32_t)(kt4 * 32) + bsel) ^ ((uint32_t)((b_r & 7) << 4)));
                uint32_t bh4[4];
                ldsm4(bh4, kb + off);
#pragma unroll
                for (int n2 = 0; n2 < 2; n2++) {
                    float* s = sc[2 * kg + n2];
                    mma_f16(s, qh[kt4], &bh4[n2 * 2]);
                    mma_f16(s, ql[kt4], &bh4[n2 * 2]);
                }
            }
        }

        if (kt == qt) {
#pragma unroll
            for (int nt = 0; nt < 8; nt++) {
                int key = kt * 64 + nt * 8 + 2 * (lane & 3);
                if (key > q0)         sc[nt][0] = -1e30f;
                if (key + 1 > q0)     sc[nt][1] = -1e30f;
                if (key > q0 + 8)     sc[nt][2] = -1e30f;
                if (key + 1 > q0 + 8) sc[nt][3] = -1e30f;
            }
        }

        float r0 = -1e30f, r1 = -1e30f;
#pragma unroll
        for (int nt = 0; nt < 8; nt++) {
            r0 = fmaxf(r0, fmaxf(sc[nt][0], sc[nt][1]));
            r1 = fmaxf(r1, fmaxf(sc[nt][2], sc[nt][3]));
        }
        r0 = fmaxf(r0, __shfl_xor_sync(0xffffffffu, r0, 1));
        r0 = fmaxf(r0, __shfl_xor_sync(0xffffffffu, r0, 2));
        r1 = fmaxf(r1, __shfl_xor_sync(0xffffffffu, r1, 1));
        r1 = fmaxf(r1, __shfl_xor_sync(0xffffffffu, r1, 2));
        float mA2 = fmaxf(mA, r0), mB2 = fmaxf(mB, r1);
        float cA = __expf(mA - mA2), cB = __expf(mB - mB2);
        mA = mA2; mB = mB2;

        float sA = 0.f, sB = 0.f;
#pragma unroll
        for (int nt = 0; nt < 8; nt++) {
            sc[nt][0] = __expf(sc[nt][0] - mA);
            sc[nt][1] = __expf(sc[nt][1] - mA);
            sc[nt][2] = __expf(sc[nt][2] - mB);
            sc[nt][3] = __expf(sc[nt][3] - mB);
            sA += sc[nt][0] + sc[nt][1];
            sB += sc[nt][2] + sc[nt][3];
        }
        sA += __shfl_xor_sync(0xffffffffu, sA, 1);
        sA += __shfl_xor_sync(0xffffffffu, sA, 2);
        sB += __shfl_xor_sync(0xffffffffu, sB, 1);
        sB += __shfl_xor_sync(0xffffffffu, sB, 2);
        lA = lA * cA + sA;
        lB = lB * cB + sB;
#pragma unroll
        for (int nt = 0; nt < 8; nt++) {
            O[nt][0] *= cA; O[nt][1] *= cA;
            O[nt][2] *= cB; O[nt][3] *= cB;
        }

        // PV: p hi only, v hi only (vt layout [d][s], non-trans ldsm)
#pragma unroll
        for (int sg = 0; sg < 4; sg++) {
            uint32_t ph[4];
            ph[0] = pack_h2(sc[2 * sg][0], sc[2 * sg][1]);
            ph[1] = pack_h2(sc[2 * sg][2], sc[2 * sg][3]);
            ph[2] = pack_h2(sc[2 * sg + 1][0], sc[2 * sg + 1][1]);
            ph[3] = pack_h2(sc[2 * sg + 1][2], sc[2 * sg + 1][3]);
#pragma unroll
            for (int dg = 0; dg < 4; dg++) {
                int b_r = dg * 16 + b_rbase;
                uint32_t off = (uint32_t)(b_r * 128) + (((uint32_t)(sg * 32) + bsel) ^ ((uint32_t)((b_r & 7) << 4)));
                uint32_t vh4[4];
                ldsm4(vh4, vb + off);
#pragma unroll
                for (int n2 = 0; n2 < 2; n2++) {
                    mma_f16(O[2 * dg + n2], ph, &vh4[n2 * 2]);
                }
            }
        }
        __syncthreads();
    }

    // epilogue: o hi fp16
    float iA = 1.f / lA, iB = 1.f / lB;
    size_t r0o = (size_t)q0 * QDIM + h * 64;
    size_t r1o = r0o + (size_t)8 * QDIM;
#pragma unroll
    for (int nt = 0; nt < 8; nt++) {
        int c = nt * 8 + 2 * (lane & 3);
        *(uint32_t*)(g_o_h + r0o + c) = pack_h2(O[nt][0] * iA, O[nt][1] * iA);
        *(uint32_t*)(g_o_h + r1o + c) = pack_h2(O[nt][2] * iB, O[nt][3] * iB);
    }
}

// ============================================================
// launch
// ============================================================
extern "C" void kernel_launch(void* const* d_in, const int* in_sizes, int n_in,
                              void* d_out, int out_size) {
    const float* x          = (const float*)d_in[0];
    const float* sinks      = (const float*)d_in[1];
    const float* norm_scale = (const float*)d_in[2];
    const float* qkv_w      = (const float*)d_in[3];
    const float* qkv_b      = (const float*)d_in[4];
    const float* out_w      = (const float*)d_in[5];
    const float* out_b      = (const float*)d_in[6];
    float* out = (float*)d_out;

    float* g_qkv_p; cudaGetSymbolAddress((void**)&g_qkv_p, g_qkv);
    __half *th, *w1, *w2, *oh;
    cudaGetSymbolAddress((void**)&th, g_t_h);
    cudaGetSymbolAddress((void**)&w1, g_w1);
    cudaGetSymbolAddress((void**)&w2, g_w2);
    cudaGetSymbolAddress((void**)&oh, g_o_h);

    cudaFuncSetAttribute(gemm_mma<false>, cudaFuncAttributeMaxDynamicSharedMemorySize, SMEM_TOTAL_GEMM);
    cudaFuncSetAttribute(gemm_mma<true>,  cudaFuncAttributeMaxDynamicSharedMemorySize, SMEM_TOTAL_GEMM);
    cudaFuncSetAttribute(attn_mma_kernel, cudaFuncAttributeMaxDynamicSharedMemorySize, ATT_SMEM_TOTAL);

    rope_tables_kernel<<<(S_TOK * 32 + 255) / 256, 256>>>();
    {
        int n4 = QKV_DIM * HID / 4;
        convert_h_kernel<<<(n4 + 255) / 256, 256>>>((const float4*)qkv_w, (uint2*)w1, n4);
    }
    {
        int n4 = HID * QDIM / 4;
        convert_h_kernel<<<(n4 + 255) / 256, 256>>>((const float4*)out_w, (uint2*)w2, n4);
    }

    rmsnorm_kernel<<<S_TOK, 256>>>(x, norm_scale);

    // qkv = t @ qkv_w^T + qkv_b   (M=1536, N=5120, K=2880)
    gemm_mma<false><<<dim3(QKV_DIM / BN, S_TOK / BM), 128, SMEM_TOTAL_GEMM>>>(
        th, w1, qkv_b, nullptr, g_qkv_p, S_TOK, QKV_DIM, HID);

    // rope + split + v transpose
    prep_attn_kernel<<<S_TOK, 128>>>();

    // tensorized attention
    attn_mma_kernel<<<dim3(S_TOK / 64, NH), 128, ATT_SMEM_TOTAL>>>(sinks);

    // y = o @ out_w^T + out_b + x   (M=1536, N=2880, K=4096)
    gemm_mma<true><<<dim3((HID + BN - 1) / BN, S_TOK / BM), 128, SMEM_TOTAL_GEMM>>>(
        oh, w2, out_b, x, out, S_TOK, HID, QDIM);
}

// round 11
// speedup vs baseline: 1.2117x; 1.0487x over previous
#include <cuda_runtime.h>
#include <cuda_fp16.h>
#include <cstdint>
#include <math.h>

// ---------------- problem constants ----------------
#define S_TOK   1536
#define HID     2880
#define NH      64
#define NKV     8
#define DH      64
#define QKV_DIM 5120
#define QDIM    4096
#define KOFF    4096
#define VOFF    4608
#define SM_SCALE 0.125f

// ---------------- scratch ----------------
__device__ float g_qkv[S_TOK * QKV_DIM];
__device__ __half g_t_h[S_TOK * HID];
__device__ __half g_w1[QKV_DIM * HID];
__device__ __half g_w2[HID * QDIM];
__device__ __half g_q_h[S_TOK * QDIM];
__device__ __half g_k_h[NKV * S_TOK * DH];
__device__ __half g_vt_h[NKV * DH * S_TOK];
__device__ __half g_o_h[S_TOK * QDIM];
__device__ float g_cos[S_TOK * 32];
__device__ float g_sin[S_TOK * 32];

// ---------------- helpers ----------------
__device__ __forceinline__ uint32_t smem_u32(const void* p) {
    uint32_t a;
    asm("{ .reg .u64 t; cvta.to.shared.u64 t, %1; cvt.u32.u64 %0, t; }" : "=r"(a) : "l"(p));
    return a;
}

__device__ __forceinline__ void ldsm4(uint32_t* r, uint32_t addr) {
    asm volatile("ldmatrix.sync.aligned.m8n8.x4.shared.b16 {%0,%1,%2,%3}, [%4];"
                 : "=r"(r[0]), "=r"(r[1]), "=r"(r[2]), "=r"(r[3]) : "r"(addr));
}

__device__ __forceinline__ void mma_f16(float* c, const uint32_t* a, const uint32_t* b) {
    asm volatile("mma.sync.aligned.m16n8k16.row.col.f32.f16.f16.f32 "
                 "{%0,%1,%2,%3}, {%4,%5,%6,%7}, {%8,%9}, {%0,%1,%2,%3};"
                 : "+f"(c[0]), "+f"(c[1]), "+f"(c[2]), "+f"(c[3])
                 : "r"(a[0]), "r"(a[1]), "r"(a[2]), "r"(a[3]), "r"(b[0]), "r"(b[1]));
}

__device__ __forceinline__ uint32_t pack_h2(float a, float b) {
    __half2 h = __floats2half2_rn(a, b);
    return *(uint32_t*)&h;
}

// ============================================================
// 1) RMSNorm -> fp16 (hi only)
// ============================================================
__global__ void rmsnorm_kernel(const float* __restrict__ x,
                               const float* __restrict__ scale) {
    int s = blockIdx.x;
    const float4* xr = (const float4*)(x + (size_t)s * HID);
    const float4* sc = (const float4*)scale;

    float ss = 0.f;
    for (int i = threadIdx.x; i < HID / 4; i += blockDim.x) {
        float4 v = xr[i];
        ss += v.x * v.x + v.y * v.y + v.z * v.z + v.w * v.w;
    }
    for (int o = 16; o > 0; o >>= 1) ss += __shfl_xor_sync(0xffffffff, ss, o);
    __shared__ float red[8];
    int wid = threadIdx.x >> 5, lid = threadIdx.x & 31;
    if (lid == 0) red[wid] = ss;
    __syncthreads();
    if (wid == 0) {
        float v = (lid < (blockDim.x >> 5)) ? red[lid] : 0.f;
        for (int o = 4; o > 0; o >>= 1) v += __shfl_xor_sync(0xffffffff, v, o);
        if (lid == 0) red[0] = v;
    }
    __syncthreads();
    float r = rsqrtf(red[0] / (float)HID + 1e-5f);

    uint2* th = (uint2*)(g_t_h + (size_t)s * HID);
    for (int i = threadIdx.x; i < HID / 4; i += blockDim.x) {
        float4 v = xr[i];
        float4 g = sc[i];
        uint2 hh;
        hh.x = pack_h2(v.x * r * g.x, v.y * r * g.y);
        hh.y = pack_h2(v.z * r * g.z, v.w * r * g.w);
        th[i] = hh;
    }
}

// ============================================================
// 2) fp32 -> fp16 convert (weights)
// ============================================================
__global__ void convert_h_kernel(const float4* __restrict__ src,
                                 uint2* __restrict__ dst, int n4) {
    int i = blockIdx.x * blockDim.x + threadIdx.x;
    if (i >= n4) return;
    float4 v = src[i];
    uint2 o;
    o.x = pack_h2(v.x, v.y);
    o.y = pack_h2(v.z, v.w);
    dst[i] = o;
}

// ============================================================
// 3) mma.sync fp16 GEMM: C = A B^T + bias (+resid)
//    CTA 128x128x64, 128 threads (2x2 warps, warp tile 64x64)
// ============================================================
#define BM 128
#define BN 128
#define BK 64
#define TILE_B 16384            // 128 rows x 128 bytes
#define STAGE_B (2 * TILE_B)    // A, B
#define GEMM_STAGES 3
#define SMEM_TOTAL_GEMM (GEMM_STAGES * STAGE_B + 1024)

__device__ __forceinline__ void load_tile_128(uint32_t sbase, const __half* __restrict__ g,
                                              int row0, int nrows, int ldk, int k0, int tid) {
#pragma unroll
    for (int u = 0; u < 8; u++) {
        int unit = u * 128 + tid;       // 0..1023
        int r = unit >> 3;
        int c16 = unit & 7;
        uint32_t off = (uint32_t)(r * 128 + ((c16 * 16) ^ ((r & 7) << 4)));
        int gr = row0 + r;
        int ok = (gr < nrows) ? 16 : 0;
        const __half* src = g + (size_t)((gr < nrows) ? gr : 0) * ldk + k0 + c16 * 8;
        asm volatile("cp.async.cg.shared.global [%0], [%1], 16, %2;"
                     :: "r"(sbase + off), "l"(src), "r"(ok) : "memory");
    }
}

__device__ __forceinline__ void load_stage(uint32_t st,
                                           const __half* A, const __half* B,
                                           int bm, int bn, int M, int N, int K, int k0, int tid) {
    load_tile_128(st,          A, bm, M, K, k0, tid);
    load_tile_128(st + TILE_B, B, bn, N, K, k0, tid);
}

template <bool RESID>
__global__ void __launch_bounds__(128, 2)
gemm_mma(const __half* __restrict__ A, const __half* __restrict__ B,
         const float* __restrict__ bias, const float* __restrict__ resid,
         float* __restrict__ C, int M, int N, int K) {
    extern __shared__ char smem_raw[];
    uint32_t sb = (smem_u32(smem_raw) + 1023u) & ~1023u;

    const int tid = threadIdx.x;
    const int wid = tid >> 5;
    const int lane = tid & 31;
    const int wm = wid & 1;        // 0..1
    const int wn = wid >> 1;       // 0..1
    const int bm = blockIdx.y * BM;
    const int bn = blockIdx.x * BN;

    float acc[4][8][4];
#pragma unroll
    for (int i = 0; i < 4; i++)
#pragma unroll
        for (int j = 0; j < 8; j++)
#pragma unroll
            for (int k = 0; k < 4; k++) acc[i][j][k] = 0.f;

    const int a_r = wm * 64 + (lane & 15);
    const uint32_t a_cx = (uint32_t)((a_r & 7) << 4);
    const int b_r = wn * 64 + ((lane >> 4) << 3) + (lane & 7);
    const uint32_t b_cx = (uint32_t)((b_r & 7) << 4);

    const int NC = K / BK;

#pragma unroll
    for (int c = 0; c < 2; c++) {
        load_stage(sb + c * STAGE_B, A, B, bm, bn, M, N, K, c * BK, tid);
        asm volatile("cp.async.commit_group;" ::: "memory");
    }

    for (int c = 0; c < NC; c++) {
        int pf = c + 2;
        if (pf < NC) {
            load_stage(sb + (pf % GEMM_STAGES) * STAGE_B, A, B, bm, bn, M, N, K, pf * BK, tid);
        }
        asm volatile("cp.async.commit_group;" ::: "memory");
        asm volatile("cp.async.wait_group 2;" ::: "memory");
        __syncthreads();

        const uint32_t st = sb + (c % GEMM_STAGES) * STAGE_B;
#pragma unroll
        for (int ks = 0; ks < 4; ks++) {
            uint32_t ah[4][4], bh[4][4];
            const uint32_t acb = (uint32_t)(ks * 32 + ((lane >> 4) << 4));
#pragma unroll
            for (int mt = 0; mt < 4; mt++) {
                uint32_t off = (uint32_t)((a_r + mt * 16) * 128) + (acb ^ a_cx);
                ldsm4(ah[mt], st + off);
            }
            const uint32_t bcb = (uint32_t)(ks * 32 + ((lane >> 3) & 1) * 16);
#pragma unroll
            for (int p = 0; p < 4; p++) {
                uint32_t off = (uint32_t)((b_r + p * 16) * 128) + (bcb ^ b_cx);
                ldsm4(bh[p], st + TILE_B + off);
            }
#pragma unroll
            for (int mt = 0; mt < 4; mt++) {
#pragma unroll
                for (int nt = 0; nt < 8; nt++) {
                    mma_f16(acc[mt][nt], ah[mt], &bh[nt >> 1][(nt & 1) * 2]);
                }
            }
        }
        __syncthreads();
    }

    const int row0 = bm + wm * 64;
    const int col0 = bn + wn * 64;
#pragma unroll
    for (int mt = 0; mt < 4; mt++) {
#pragma unroll
        for (int nt = 0; nt < 8; nt++) {
            int r = row0 + mt * 16 + (lane >> 2);
            int c0 = col0 + nt * 8 + (lane & 3) * 2;
            if (c0 < N) {
                float bx = bias[c0], by = bias[c0 + 1];
                float2 v0, v1;
                v0.x = acc[mt][nt][0] + bx; v0.y = acc[mt][nt][1] + by;
                v1.x = acc[mt][nt][2] + bx; v1.y = acc[mt][nt][3] + by;
                if (RESID) {
                    const float2 x0 = *(const float2*)(resid + (size_t)r * N + c0);
                    const float2 x1 = *(const float2*)(resid + (size_t)(r + 8) * N + c0);
                    v0.x += x0.x; v0.y += x0.y;
                    v1.x += x1.x; v1.y += x1.y;
                }
                *(float2*)(C + (size_t)r * N + c0) = v0;
                *(float2*)(C + (size_t)(r + 8) * N + c0) = v1;
            }
        }
    }
}

// ============================================================
// 4) YaRN RoPE tables (fp64, matches reference)
// ============================================================
__global__ void rope_tables_kernel() {
    int gid = blockIdx.x * blockDim.x + threadIdx.x;
    if (gid >= S_TOK * 32) return;
    int s = gid >> 5;
    int i = gid & 31;
    const double TWO_PI = 6.283185307179586;
    double freq = pow(150000.0, (double)(2 * i) / 64.0);
    double conc = 0.1 * log(32.0) + 1.0;
    double lo = 32.0 * log(4096.0 / (32.0 * TWO_PI)) / log(150000.0);
    double hi = 32.0 * log(4096.0 / (1.0 * TWO_PI)) / log(150000.0);
    double interp = 1.0 / (32.0 * freq);
    double extrap = 1.0 / freq;
    double ramp = ((double)i - lo) / (hi - lo);
    double mask = 1.0 - fmin(fmax(ramp, 0.0), 1.0);
    double invf = interp * (1.0 - mask) + extrap * mask;
    double f = (double)s * invf;
    g_cos[gid] = (float)(cos(f) * conc);
    g_sin[gid] = (float)(sin(f) * conc);
}

// ============================================================
// 5) prep: rope + scale; q hi, k hi, v hi transposed
// ============================================================
__global__ void __launch_bounds__(128)
prep_attn_kernel() {
    int s = blockIdx.x;
    int tid = threadIdx.x;
    __shared__ float cs[32], sn[32];
    if (tid < 32) { cs[tid] = g_cos[s * 32 + tid]; sn[tid] = g_sin[s * 32 + tid]; }
    __syncthreads();
    const float* row = g_qkv + (size_t)s * QKV_DIM;

    // q: 64 heads x 32 rotation pairs, scaled, hi only
    for (int i = tid; i < 2048; i += 128) {
        int hh = i >> 5, d = i & 31;
        float x1 = row[hh * 64 + d], x2 = row[hh * 64 + 32 + d];
        float c = cs[d], ss = sn[d];
        float r1 = (x1 * c - x2 * ss) * SM_SCALE;
        float r2 = (x2 * c + x1 * ss) * SM_SCALE;
        size_t o = (size_t)s * QDIM + hh * 64 + d;
        g_q_h[o]      = __float2half_rn(r1);
        g_q_h[o + 32] = __float2half_rn(r2);
    }
    // k: 8 kv heads x 32 pairs, layout [kv][s][64], hi only
    for (int i = tid; i < 256; i += 128) {
        int kvh = i >> 5, d = i & 31;
        float x1 = row[KOFF + kvh * 64 + d], x2 = row[KOFF + kvh * 64 + 32 + d];
        float c = cs[d], ss = sn[d];
        size_t o = (size_t)kvh * S_TOK * DH + (size_t)s * DH + d;
        g_k_h[o]      = __float2half_rn(x1 * c - x2 * ss);
        g_k_h[o + 32] = __float2half_rn(x2 * c + x1 * ss);
    }
    // v: transpose -> [kv][d][s], hi only
    for (int i = tid; i < 512; i += 128) {
        int kvh = i >> 6, d = i & 63;
        float v = row[VOFF + kvh * 64 + d];
        g_vt_h[(size_t)kvh * DH * S_TOK + (size_t)d * S_TOK + s] = __float2half_rn(v);
    }
}

// ============================================================
// 6) tensorized flash attention with sinks
//    block: 128 q rows x 1 head, 4 warps (32 rows each, mt=2)
// ============================================================
#define ATT_STAGE 16384         // k 8KB + vt 8KB
#define ATT_SMEM_TOTAL (1024 + 16384 + 2 * ATT_STAGE)

__device__ __forceinline__ void stage128q(uint32_t sbase, const __half* __restrict__ g,
                                          int row_stride, int tid) {
#pragma unroll
    for (int u = 0; u < 8; u++) {
        int unit = u * 128 + tid;
        int r = unit >> 3, c16 = unit & 7;
        uint32_t off = (uint32_t)(r * 128 + ((c16 * 16) ^ ((r & 7) << 4)));
        const __half* src = g + (size_t)r * row_stride + c16 * 8;
        asm volatile("cp.async.cg.shared.global [%0], [%1], 16;"
                     :: "r"(sbase + off), "l"(src) : "memory");
    }
}

__device__ __forceinline__ void stage64(uint32_t sbase, const __half* __restrict__ g,
                                        int row_stride, int tid) {
#pragma unroll
    for (int u = 0; u < 4; u++) {
        int unit = u * 128 + tid;
        int r = unit >> 3, c16 = unit & 7;
        uint32_t off = (uint32_t)(r * 128 + ((c16 * 16) ^ ((r & 7) << 4)));
        const __half* src = g + (size_t)r * row_stride + c16 * 8;
        asm volatile("cp.async.cg.shared.global [%0], [%1], 16;"
                     :: "r"(sbase + off), "l"(src) : "memory");
    }
}

__device__ __forceinline__ void stage_kv(uint32_t base, int kt, int kv, int tid) {
    const __half* kh = g_k_h + (size_t)kv * S_TOK * DH + (size_t)kt * 64 * DH;
    const __half* vh = g_vt_h + (size_t)kv * DH * S_TOK + kt * 64;
    stage64(base,        kh, DH, tid);
    stage64(base + 8192, vh, S_TOK, tid);
}

__global__ void __launch_bounds__(128)
attn_mma_kernel(const float* __restrict__ sinks) {
    extern __shared__ char sraw[];
    uint32_t sb = (smem_u32(sraw) + 1023u) & ~1023u;
    const uint32_t QB = sb, KVB = sb + 16384;

    const int qt = (int)gridDim.x - 1 - (int)blockIdx.x;   // long blocks first
    const int h = blockIdx.y, kv = h & 7;
    const int tid = threadIdx.x, w = tid >> 5, lane = tid & 31;

    stage128q(QB, g_q_h + (size_t)(qt * 128) * QDIM + h * 64, QDIM, tid);
    stage_kv(KVB, 0, kv, tid);
    asm volatile("cp.async.commit_group;" ::: "memory");
    asm volatile("cp.async.wait_group 0;" ::: "memory");
    __syncthreads();

    // persistent q fragments: 2 m16 blocks x 4 k16 slices
    uint32_t qh[2][4][4];
#pragma unroll
    for (int mt = 0; mt < 2; mt++) {
        int a_r = w * 32 + mt * 16 + (lane & 15);
        uint32_t ax = (uint32_t)((a_r & 7) << 4);
#pragma unroll
        for (int kt4 = 0; kt4 < 4; kt4++) {
            uint32_t cb = (uint32_t)(kt4 * 32 + ((lane >> 4) << 4));
            uint32_t off = (uint32_t)(a_r * 128) + (cb ^ ax);
            ldsm4(qh[mt][kt4], QB + off);
        }
    }

    float O[2][8][4];
#pragma unroll
    for (int mt = 0; mt < 2; mt++)
#pragma unroll
        for (int nt = 0; nt < 8; nt++)
#pragma unroll
            for (int j = 0; j < 4; j++) O[mt][nt][j] = 0.f;

    float snk = sinks[h];
    float mxA[2] = {snk, snk}, mxB[2] = {snk, snk};
    float lA[2] = {1.f, 1.f}, lB[2] = {1.f, 1.f};

    const int rbase = qt * 128 + w * 32 + (lane >> 2);   // + mt*16 (+8)
    const int b_rbase = ((lane >> 4) << 3) + (lane & 7);
    const uint32_t bsel = (uint32_t)(((lane >> 3) & 1) * 16);
    const int KT = 2 * qt + 2;

    for (int kt = 0; kt < KT; kt++) {
        if (kt + 1 < KT)
            stage_kv(KVB + ((kt + 1) & 1) * ATT_STAGE, kt + 1, kv, tid);
        asm volatile("cp.async.commit_group;" ::: "memory");
        asm volatile("cp.async.wait_group 1;" ::: "memory");
        __syncthreads();

        const uint32_t kb = KVB + (kt & 1) * ATT_STAGE;
        const uint32_t vb = kb + 8192;

        float sc[2][8][4];
#pragma unroll
        for (int mt = 0; mt < 2; mt++)
#pragma unroll
            for (int nt = 0; nt < 8; nt++)
#pragma unroll
                for (int j = 0; j < 4; j++) sc[mt][nt][j] = 0.f;

        // QK (q hi only)
#pragma unroll
        for (int kt4 = 0; kt4 < 4; kt4++) {
#pragma unroll
            for (int kg = 0; kg < 4; kg++) {
                int b_r = kg * 16 + b_rbase;
                uint32_t off = (uint32_t)(b_r * 128) + (((uint32_t)(kt4 * 32) + bsel) ^ ((uint32_t)((b_r & 7) << 4)));
                uint32_t bh4[4];
                ldsm4(bh4, kb + off);
#pragma unroll
                for (int mt = 0; mt < 2; mt++) {
#pragma unroll
                    for (int n2 = 0; n2 < 2; n2++) {
                        mma_f16(sc[mt][2 * kg + n2], qh[mt][kt4], &bh4[n2 * 2]);
                    }
                }
            }
        }

        // causal mask (only the tiles that can cross the diagonal)
        if (kt >= 2 * qt) {
#pragma unroll
            for (int mt = 0; mt < 2; mt++) {
                int row = rbase + mt * 16;
#pragma unroll
                for (int nt = 0; nt < 8; nt++) {
                    int key = kt * 64 + nt * 8 + 2 * (lane & 3);
                    if (key > row)         sc[mt][nt][0] = -1e30f;
                    if (key + 1 > row)     sc[mt][nt][1] = -1e30f;
                    if (key > row + 8)     sc[mt][nt][2] = -1e30f;
                    if (key + 1 > row + 8) sc[mt][nt][3] = -1e30f;
                }
            }
        }

        // online softmax per mt
#pragma unroll
        for (int mt = 0; mt < 2; mt++) {
            float r0 = -1e30f, r1 = -1e30f;
#pragma unroll
            for (int nt = 0; nt < 8; nt++) {
                r0 = fmaxf(r0, fmaxf(sc[mt][nt][0], sc[mt][nt][1]));
                r1 = fmaxf(r1, fmaxf(sc[mt][nt][2], sc[mt][nt][3]));
            }
            r0 = fmaxf(r0, __shfl_xor_sync(0xffffffffu, r0, 1));
            r0 = fmaxf(r0, __shfl_xor_sync(0xffffffffu, r0, 2));
            r1 = fmaxf(r1, __shfl_xor_sync(0xffffffffu, r1, 1));
            r1 = fmaxf(r1, __shfl_xor_sync(0xffffffffu, r1, 2));
            float mA2 = fmaxf(mxA[mt], r0), mB2 = fmaxf(mxB[mt], r1);
            float cA = __expf(mxA[mt] - mA2), cB = __expf(mxB[mt] - mB2);
            mxA[mt] = mA2; mxB[mt] = mB2;

            float sA = 0.f, sB = 0.f;
#pragma unroll
            for (int nt = 0; nt < 8; nt++) {
                sc[mt][nt][0] = __expf(sc[mt][nt][0] - mA2);
                sc[mt][nt][1] = __expf(sc[mt][nt][1] - mA2);
                sc[mt][nt][2] = __expf(sc[mt][nt][2] - mB2);
                sc[mt][nt][3] = __expf(sc[mt][nt][3] - mB2);
                sA += sc[mt][nt][0] + sc[mt][nt][1];
                sB += sc[mt][nt][2] + sc[mt][nt][3];
            }
            sA += __shfl_xor_sync(0xffffffffu, sA, 1);
            sA += __shfl_xor_sync(0xffffffffu, sA, 2);
            sB += __shfl_xor_sync(0xffffffffu, sB, 1);
            sB += __shfl_xor_sync(0xffffffffu, sB, 2);
            lA[mt] = lA[mt] * cA + sA;
            lB[mt] = lB[mt] * cB + sB;
#pragma unroll
            for (int nt = 0; nt < 8; nt++) {
                O[mt][nt][0] *= cA; O[mt][nt][1] *= cA;
                O[mt][nt][2] *= cB; O[mt][nt][3] *= cB;
            }
        }

        // PV: p hi only, v hi only (vt layout [d][s], non-trans ldsm)
#pragma unroll
        for (int sg = 0; sg < 4; sg++) {
            uint32_t ph[2][4];
#pragma unroll
            for (int mt = 0; mt < 2; mt++) {
                ph[mt][0] = pack_h2(sc[mt][2 * sg][0], sc[mt][2 * sg][1]);
                ph[mt][1] = pack_h2(sc[mt][2 * sg][2], sc[mt][2 * sg][3]);
                ph[mt][2] = pack_h2(sc[mt][2 * sg + 1][0], sc[mt][2 * sg + 1][1]);
                ph[mt][3] = pack_h2(sc[mt][2 * sg + 1][2], sc[mt][2 * sg + 1][3]);
            }
#pragma unroll
            for (int dg = 0; dg < 4; dg++) {
                int b_r = dg * 16 + b_rbase;
                uint32_t off = (uint32_t)(b_r * 128) + (((uint32_t)(sg * 32) + bsel) ^ ((uint32_t)((b_r & 7) << 4)));
                uint32_t vh4[4];
                ldsm4(vh4, vb + off);
#pragma unroll
                for (int mt = 0; mt < 2; mt++) {
#pragma unroll
                    for (int n2 = 0; n2 < 2; n2++) {
                        mma_f16(O[mt][2 * dg + n2], ph[mt], &vh4[n2 * 2]);
                    }
                }
            }
        }
        __syncthreads();
    }

    // epilogue: o hi fp16
#pragma unroll
    for (int mt = 0; mt < 2; mt++) {
        float iA = 1.f / lA[mt], iB = 1.f / lB[mt];
        int row = rbase + mt * 16;
        size_t r0o = (size_t)row * QDIM + h * 64;
        size_t r1o = r0o + (size_t)8 * QDIM;
#pragma unroll
        for (int nt = 0; nt < 8; nt++) {
            int c = nt * 8 + 2 * (lane & 3);
            *(uint32_t*)(g_o_h + r0o + c) = pack_h2(O[mt][nt][0] * iA, O[mt][nt][1] * iA);
            *(uint32_t*)(g_o_h + r1o + c) = pack_h2(O[mt][nt][2] * iB, O[mt][nt][3] * iB);
        }
    }
}

// ============================================================
// launch
// ============================================================
extern "C" void kernel_launch(void* const* d_in, const int* in_sizes, int n_in,
                              void* d_out, int out_size) {
    const float* x          = (const float*)d_in[0];
    const float* sinks      = (const float*)d_in[1];
    const float* norm_scale = (const float*)d_in[2];
    const float* qkv_w      = (const float*)d_in[3];
    const float* qkv_b      = (const float*)d_in[4];
    const float* out_w      = (const float*)d_in[5];
    const float* out_b      = (const float*)d_in[6];
    float* out = (float*)d_out;

    float* g_qkv_p; cudaGetSymbolAddress((void**)&g_qkv_p, g_qkv);
    __half *th, *w1, *w2, *oh;
    cudaGetSymbolAddress((void**)&th, g_t_h);
    cudaGetSymbolAddress((void**)&w1, g_w1);
    cudaGetSymbolAddress((void**)&w2, g_w2);
    cudaGetSymbolAddress((void**)&oh, g_o_h);

    cudaFuncSetAttribute(gemm_mma<false>, cudaFuncAttributeMaxDynamicSharedMemorySize, SMEM_TOTAL_GEMM);
    cudaFuncSetAttribute(gemm_mma<true>,  cudaFuncAttributeMaxDynamicSharedMemorySize, SMEM_TOTAL_GEMM);
    cudaFuncSetAttribute(attn_mma_kernel, cudaFuncAttributeMaxDynamicSharedMemorySize, ATT_SMEM_TOTAL);

    rope_tables_kernel<<<(S_TOK * 32 + 255) / 256, 256>>>();
    {
        int n4 = QKV_DIM * HID / 4;
        convert_h_kernel<<<(n4 + 255) / 256, 256>>>((const float4*)qkv_w, (uint2*)w1, n4);
    }
    {
        int n4 = HID * QDIM / 4;
        convert_h_kernel<<<(n4 + 255) / 256, 256>>>((const float4*)out_w, (uint2*)w2, n4);
    }

    rmsnorm_kernel<<<S_TOK, 256>>>(x, norm_scale);

    // qkv = t @ qkv_w^T + qkv_b   (M=1536, N=5120, K=2880)
    gemm_mma<false><<<dim3(QKV_DIM / BN, S_TOK / BM), 128, SMEM_TOTAL_GEMM>>>(
        th, w1, qkv_b, nullptr, g_qkv_p, S_TOK, QKV_DIM, HID);

    // rope + split + v transpose
    prep_attn_kernel<<<S_TOK, 128>>>();

    // tensorized attention (128-row q tiles)
    attn_mma_kernel<<<dim3(S_TOK / 128, NH), 128, ATT_SMEM_TOTAL>>>(sinks);

    // y = o @ out_w^T + out_b + x   (M=1536, N=2880, K=4096)
    gemm_mma<true><<<dim3((HID + BN - 1) / BN, S_TOK / BM), 128, SMEM_TOTAL_GEMM>>>(
        oh, w2, out_b, x, out, S_TOK, HID, QDIM);
}

// round 12
// speedup vs baseline: 1.2608x; 1.0406x over previous
#include <cuda_runtime.h>
#include <cuda_fp16.h>
#include <cstdint>
#include <math.h>

// ---------------- problem constants ----------------
#define S_TOK   1536
#define HID     2880
#define NH      64
#define NKV     8
#define DH      64
#define QKV_DIM 5120
#define QDIM    4096
#define KOFF    4096
#define VOFF    4608
#define SM_SCALE 0.125f

// ---------------- scratch ----------------
__device__ __half g_t_h[S_TOK * HID];
__device__ __half g_w1[QKV_DIM * HID];
__device__ __half g_w2[HID * QDIM];
__device__ __half g_q_h[S_TOK * QDIM];
__device__ __half g_k_h[NKV * S_TOK * DH];
__device__ __half g_vt_h[NKV * DH * S_TOK];
__device__ __half g_o_h[S_TOK * QDIM];
__device__ float g_cos[S_TOK * 32];
__device__ float g_sin[S_TOK * 32];

// ---------------- helpers ----------------
__device__ __forceinline__ uint32_t smem_u32(const void* p) {
    uint32_t a;
    asm("{ .reg .u64 t; cvta.to.shared.u64 t, %1; cvt.u32.u64 %0, t; }" : "=r"(a) : "l"(p));
    return a;
}

__device__ __forceinline__ void ldsm4(uint32_t* r, uint32_t addr) {
    asm volatile("ldmatrix.sync.aligned.m8n8.x4.shared.b16 {%0,%1,%2,%3}, [%4];"
                 : "=r"(r[0]), "=r"(r[1]), "=r"(r[2]), "=r"(r[3]) : "r"(addr));
}

__device__ __forceinline__ void mma_f16(float* c, const uint32_t* a, const uint32_t* b) {
    asm volatile("mma.sync.aligned.m16n8k16.row.col.f32.f16.f16.f32 "
                 "{%0,%1,%2,%3}, {%4,%5,%6,%7}, {%8,%9}, {%0,%1,%2,%3};"
                 : "+f"(c[0]), "+f"(c[1]), "+f"(c[2]), "+f"(c[3])
                 : "r"(a[0]), "r"(a[1]), "r"(a[2]), "r"(a[3]), "r"(b[0]), "r"(b[1]));
}

__device__ __forceinline__ uint32_t pack_h2(float a, float b) {
    __half2 h = __floats2half2_rn(a, b);
    return *(uint32_t*)&h;
}

// ============================================================
// 1) RMSNorm -> fp16
// ============================================================
__global__ void rmsnorm_kernel(const float* __restrict__ x,
                               const float* __restrict__ scale) {
    int s = blockIdx.x;
    const float4* xr = (const float4*)(x + (size_t)s * HID);
    const float4* sc = (const float4*)scale;

    float ss = 0.f;
    for (int i = threadIdx.x; i < HID / 4; i += blockDim.x) {
        float4 v = xr[i];
        ss += v.x * v.x + v.y * v.y + v.z * v.z + v.w * v.w;
    }
    for (int o = 16; o > 0; o >>= 1) ss += __shfl_xor_sync(0xffffffff, ss, o);
    __shared__ float red[8];
    int wid = threadIdx.x >> 5, lid = threadIdx.x & 31;
    if (lid == 0) red[wid] = ss;
    __syncthreads();
    if (wid == 0) {
        float v = (lid < (blockDim.x >> 5)) ? red[lid] : 0.f;
        for (int o = 4; o > 0; o >>= 1) v += __shfl_xor_sync(0xffffffff, v, o);
        if (lid == 0) red[0] = v;
    }
    __syncthreads();
    float r = rsqrtf(red[0] / (float)HID + 1e-5f);

    uint2* th = (uint2*)(g_t_h + (size_t)s * HID);
    for (int i = threadIdx.x; i < HID / 4; i += blockDim.x) {
        float4 v = xr[i];
        float4 g = sc[i];
        uint2 hh;
        hh.x = pack_h2(v.x * r * g.x, v.y * r * g.y);
        hh.y = pack_h2(v.z * r * g.z, v.w * r * g.w);
        th[i] = hh;
    }
}

// ============================================================
// 2) fp32 -> fp16 convert (weights)
// ============================================================
__global__ void convert_h_kernel(const float4* __restrict__ src,
                                 uint2* __restrict__ dst, int n4) {
    int i = blockIdx.x * blockDim.x + threadIdx.x;
    if (i >= n4) return;
    float4 v = src[i];
    uint2 o;
    o.x = pack_h2(v.x, v.y);
    o.y = pack_h2(v.z, v.w);
    dst[i] = o;
}

// ============================================================
// 3) YaRN RoPE tables (fp64, matches reference) — runs FIRST
// ============================================================
__global__ void rope_tables_kernel() {
    int gid = blockIdx.x * blockDim.x + threadIdx.x;
    if (gid >= S_TOK * 32) return;
    int s = gid >> 5;
    int i = gid & 31;
    const double TWO_PI = 6.283185307179586;
    double freq = pow(150000.0, (double)(2 * i) / 64.0);
    double conc = 0.1 * log(32.0) + 1.0;
    double lo = 32.0 * log(4096.0 / (32.0 * TWO_PI)) / log(150000.0);
    double hi = 32.0 * log(4096.0 / (1.0 * TWO_PI)) / log(150000.0);
    double interp = 1.0 / (32.0 * freq);
    double extrap = 1.0 / freq;
    double ramp = ((double)i - lo) / (hi - lo);
    double mask = 1.0 - fmin(fmax(ramp, 0.0), 1.0);
    double invf = interp * (1.0 - mask) + extrap * mask;
    double f = (double)s * invf;
    g_cos[gid] = (float)(cos(f) * conc);
    g_sin[gid] = (float)(sin(f) * conc);
}

// ============================================================
// 4) mma.sync fp16 GEMM: CTA 128x128x64, 128 threads, 64x64 warp tile
//    MODE 0: C fp32 = A B^T + bias + resid (out proj)
//    MODE 1: qkv — fused bias + rope + scale, fp16 stores to q/k/vt
// ============================================================
#define BM 128
#define BN 128
#define BK 64
#define TILE_B 16384
#define STAGE_B (2 * TILE_B)
#define GEMM_STAGES 3
#define SMEM_TOTAL_GEMM (GEMM_STAGES * STAGE_B + 1024)

__device__ __forceinline__ void load_tile_128(uint32_t sbase, const __half* __restrict__ g,
                                              int row0, int nrows, int ldk, int k0, int tid) {
#pragma unroll
    for (int u = 0; u < 8; u++) {
        int unit = u * 128 + tid;
        int r = unit >> 3;
        int c16 = unit & 7;
        uint32_t off = (uint32_t)(r * 128 + ((c16 * 16) ^ ((r & 7) << 4)));
        int gr = row0 + r;
        int ok = (gr < nrows) ? 16 : 0;
        const __half* src = g + (size_t)((gr < nrows) ? gr : 0) * ldk + k0 + c16 * 8;
        asm volatile("cp.async.cg.shared.global [%0], [%1], 16, %2;"
                     :: "r"(sbase + off), "l"(src), "r"(ok) : "memory");
    }
}

__device__ __forceinline__ void load_stage(uint32_t st,
                                           const __half* A, const __half* B,
                                           int bm, int bn, int M, int N, int K, int k0, int tid) {
    load_tile_128(st,          A, bm, M, K, k0, tid);
    load_tile_128(st + TILE_B, B, bn, N, K, k0, tid);
}

template <int MODE>
__global__ void __launch_bounds__(128, 2)
gemm_mma(const __half* __restrict__ A, const __half* __restrict__ B,
         const float* __restrict__ bias, const float* __restrict__ resid,
         float* __restrict__ C, int M, int N, int K) {
    extern __shared__ char smem_raw[];
    uint32_t sb = (smem_u32(smem_raw) + 1023u) & ~1023u;

    const int tid = threadIdx.x;
    const int wid = tid >> 5;
    const int lane = tid & 31;
    const int wm = wid & 1;
    const int wn = wid >> 1;
    const int bm = blockIdx.y * BM;
    const int bn = blockIdx.x * BN;

    float acc[4][8][4];
#pragma unroll
    for (int i = 0; i < 4; i++)
#pragma unroll
        for (int j = 0; j < 8; j++)
#pragma unroll
            for (int k = 0; k < 4; k++) acc[i][j][k] = 0.f;

    const int a_r = wm * 64 + (lane & 15);
    const uint32_t a_cx = (uint32_t)((a_r & 7) << 4);
    const int b_r = wn * 64 + ((lane >> 4) << 3) + (lane & 7);
    const uint32_t b_cx = (uint32_t)((b_r & 7) << 4);

    const int NC = K / BK;

#pragma unroll
    for (int c = 0; c < 2; c++) {
        load_stage(sb + c * STAGE_B, A, B, bm, bn, M, N, K, c * BK, tid);
        asm volatile("cp.async.commit_group;" ::: "memory");
    }

    for (int c = 0; c < NC; c++) {
        int pf = c + 2;
        if (pf < NC) {
            load_stage(sb + (pf % GEMM_STAGES) * STAGE_B, A, B, bm, bn, M, N, K, pf * BK, tid);
        }
        asm volatile("cp.async.commit_group;" ::: "memory");
        asm volatile("cp.async.wait_group 2;" ::: "memory");
        __syncthreads();

        const uint32_t st = sb + (c % GEMM_STAGES) * STAGE_B;
#pragma unroll
        for (int ks = 0; ks < 4; ks++) {
            uint32_t ah[4][4], bh[4][4];
            const uint32_t acb = (uint32_t)(ks * 32 + ((lane >> 4) << 4));
#pragma unroll
            for (int mt = 0; mt < 4; mt++) {
                uint32_t off = (uint32_t)((a_r + mt * 16) * 128) + (acb ^ a_cx);
                ldsm4(ah[mt], st + off);
            }
            const uint32_t bcb = (uint32_t)(ks * 32 + ((lane >> 3) & 1) * 16);
#pragma unroll
            for (int p = 0; p < 4; p++) {
                uint32_t off = (uint32_t)((b_r + p * 16) * 128) + (bcb ^ b_cx);
                ldsm4(bh[p], st + TILE_B + off);
            }
#pragma unroll
            for (int mt = 0; mt < 4; mt++) {
#pragma unroll
                for (int nt = 0; nt < 8; nt++) {
                    mma_f16(acc[mt][nt], ah[mt], &bh[nt >> 1][(nt & 1) * 2]);
                }
            }
        }
        __syncthreads();
    }

    const int row0 = bm + wm * 64;
    const int col0 = bn + wn * 64;

    if (MODE == 0) {
#pragma unroll
        for (int mt = 0; mt < 4; mt++) {
#pragma unroll
            for (int nt = 0; nt < 8; nt++) {
                int r = row0 + mt * 16 + (lane >> 2);
                int c0 = col0 + nt * 8 + (lane & 3) * 2;
                if (c0 < N) {
                    float bx = bias[c0], by = bias[c0 + 1];
                    float2 v0, v1;
                    v0.x = acc[mt][nt][0] + bx; v0.y = acc[mt][nt][1] + by;
                    v1.x = acc[mt][nt][2] + bx; v1.y = acc[mt][nt][3] + by;
                    const float2 x0 = *(const float2*)(resid + (size_t)r * N + c0);
                    const float2 x1 = *(const float2*)(resid + (size_t)(r + 8) * N + c0);
                    v0.x += x0.x; v0.y += x0.y;
                    v1.x += x1.x; v1.y += x1.y;
                    *(float2*)(C + (size_t)r * N + c0) = v0;
                    *(float2*)(C + (size_t)(r + 8) * N + c0) = v1;
                }
            }
        }
    } else {
        // fused qkv epilogue: warp covers one 64-col head block
        const int head_blk = col0 >> 6;   // 0..79
        if (head_blk < 64) {
            // ---- Q: rope + SM_SCALE, write g_q_h[row][head*64 + d] ----
#pragma unroll
            for (int mt = 0; mt < 4; mt++) {
                int r = row0 + mt * 16 + (lane >> 2);
#pragma unroll
                for (int nt = 0; nt < 4; nt++) {
                    int d = nt * 8 + (lane & 3) * 2;           // 0..31
                    int cA = col0 + d, cB = cA + 32;
                    float b1x = bias[cA], b1y = bias[cA + 1];
                    float b2x = bias[cB], b2y = bias[cB + 1];
                    float2 c0v = *(const float2*)(g_cos + r * 32 + d);
                    float2 s0v = *(const float2*)(g_sin + r * 32 + d);
                    float2 c1v = *(const float2*)(g_cos + (r + 8) * 32 + d);
                    float2 s1v = *(const float2*)(g_sin + (r + 8) * 32 + d);
                    // row r
                    float x1a = acc[mt][nt][0] + b1x, x1b = acc[mt][nt][1] + b1y;
                    float x2a = acc[mt][nt + 4][0] + b2x, x2b = acc[mt][nt + 4][1] + b2y;
                    size_t o = (size_t)r * QDIM + head_blk * 64 + d;
                    *(uint32_t*)(g_q_h + o) =
                        pack_h2((x1a * c0v.x - x2a * s0v.x) * SM_SCALE,
                                (x1b * c0v.y - x2b * s0v.y) * SM_SCALE);
                    *(uint32_t*)(g_q_h + o + 32) =
                        pack_h2((x2a * c0v.x + x1a * s0v.x) * SM_SCALE,
                                (x2b * c0v.y + x1b * s0v.y) * SM_SCALE);
                    // row r+8
                    float y1a = acc[mt][nt][2] + b1x, y1b = acc[mt][nt][3] + b1y;
                    float y2a = acc[mt][nt + 4][2] + b2x, y2b = acc[mt][nt + 4][3] + b2y;
                    size_t o8 = o + (size_t)8 * QDIM;
                    *(uint32_t*)(g_q_h + o8) =
                        pack_h2((y1a * c1v.x - y2a * s1v.x) * SM_SCALE,
                                (y1b * c1v.y - y2b * s1v.y) * SM_SCALE);
                    *(uint32_t*)(g_q_h + o8 + 32) =
                        pack_h2((y2a * c1v.x + y1a * s1v.x) * SM_SCALE,
                                (y2b * c1v.y + y1b * s1v.y) * SM_SCALE);
                }
            }
        } else if (head_blk < 72) {
            // ---- K: rope, write g_k_h[kv][row][d] ----
            const int kvh = head_blk - 64;
#pragma unroll
            for (int mt = 0; mt < 4; mt++) {
                int r = row0 + mt * 16 + (lane >> 2);
#pragma unroll
                for (int nt = 0; nt < 4; nt++) {
                    int d = nt * 8 + (lane & 3) * 2;
                    int cA = col0 + d, cB = cA + 32;
                    float b1x = bias[cA], b1y = bias[cA + 1];
                    float b2x = bias[cB], b2y = bias[cB + 1];
                    float2 c0v = *(const float2*)(g_cos + r * 32 + d);
                    float2 s0v = *(const float2*)(g_sin + r * 32 + d);
                    float2 c1v = *(const float2*)(g_cos + (r + 8) * 32 + d);
                    float2 s1v = *(const float2*)(g_sin + (r + 8) * 32 + d);
                    float x1a = acc[mt][nt][0] + b1x, x1b = acc[mt][nt][1] + b1y;
                    float x2a = acc[mt][nt + 4][0] + b2x, x2b = acc[mt][nt + 4][1] + b2y;
                    size_t o = (size_t)kvh * S_TOK * DH + (size_t)r * DH + d;
                    *(uint32_t*)(g_k_h + o) =
                        pack_h2(x1a * c0v.x - x2a * s0v.x, x1b * c0v.y - x2b * s0v.y);
                    *(uint32_t*)(g_k_h + o + 32) =
                        pack_h2(x2a * c0v.x + x1a * s0v.x, x2b * c0v.y + x1b * s0v.y);
                    float y1a = acc[mt][nt][2] + b1x, y1b = acc[mt][nt][3] + b1y;
                    float y2a = acc[mt][nt + 4][2] + b2x, y2b = acc[mt][nt + 4][3] + b2y;
                    size_t o8 = o + (size_t)8 * DH;
                    *(uint32_t*)(g_k_h + o8) =
                        pack_h2(y1a * c1v.x - y2a * s1v.x, y1b * c1v.y - y2b * s1v.y);
                    *(uint32_t*)(g_k_h + o8 + 32) =
                        pack_h2(y2a * c1v.x + y1a * s1v.x, y2b * c1v.y + y1b * s1v.y);
                }
            }
        } else {
            // ---- V: bias only, transposed store g_vt_h[kv][d][row] ----
            const int kvh = head_blk - 72;
            __half* vt = g_vt_h + (size_t)kvh * DH * S_TOK;
#pragma unroll
            for (int mt = 0; mt < 4; mt++) {
                int r = row0 + mt * 16 + (lane >> 2);
#pragma unroll
                for (int nt = 0; nt < 8; nt++) {
                    int d = nt * 8 + (lane & 3) * 2;
                    float bx = bias[col0 + d], by = bias[col0 + d + 1];
                    vt[(size_t)d * S_TOK + r]           = __float2half_rn(acc[mt][nt][0] + bx);
                    vt[(size_t)(d + 1) * S_TOK + r]     = __float2half_rn(acc[mt][nt][1] + by);
                    vt[(size_t)d * S_TOK + r + 8]       = __float2half_rn(acc[mt][nt][2] + bx);
                    vt[(size_t)(d + 1) * S_TOK + r + 8] = __float2half_rn(acc[mt][nt][3] + by);
                }
            }
        }
    }
}

// ============================================================
// 5) tensorized flash attention with sinks
//    block: 128 q rows x 1 head, 4 warps (32 rows each, mt=2)
// ============================================================
#define ATT_STAGE 16384
#define ATT_SMEM_TOTAL (1024 + 16384 + 2 * ATT_STAGE)

__device__ __forceinline__ void stage128q(uint32_t sbase, const __half* __restrict__ g,
                                          int row_stride, int tid) {
#pragma unroll
    for (int u = 0; u < 8; u++) {
        int unit = u * 128 + tid;
        int r = unit >> 3, c16 = unit & 7;
        uint32_t off = (uint32_t)(r * 128 + ((c16 * 16) ^ ((r & 7) << 4)));
        const __half* src = g + (size_t)r * row_stride + c16 * 8;
        asm volatile("cp.async.cg.shared.global [%0], [%1], 16;"
                     :: "r"(sbase + off), "l"(src) : "memory");
    }
}

__device__ __forceinline__ void stage64(uint32_t sbase, const __half* __restrict__ g,
                                        int row_stride, int tid) {
#pragma unroll
    for (int u = 0; u < 4; u++) {
        int unit = u * 128 + tid;
        int r = unit >> 3, c16 = unit & 7;
        uint32_t off = (uint32_t)(r * 128 + ((c16 * 16) ^ ((r & 7) << 4)));
        const __half* src = g + (size_t)r * row_stride + c16 * 8;
        asm volatile("cp.async.cg.shared.global [%0], [%1], 16;"
                     :: "r"(sbase + off), "l"(src) : "memory");
    }
}

__device__ __forceinline__ void stage_kv(uint32_t base, int kt, int kv, int tid) {
    const __half* kh = g_k_h + (size_t)kv * S_TOK * DH + (size_t)kt * 64 * DH;
    const __half* vh = g_vt_h + (size_t)kv * DH * S_TOK + kt * 64;
    stage64(base,        kh, DH, tid);
    stage64(base + 8192, vh, S_TOK, tid);
}

__global__ void __launch_bounds__(128)
attn_mma_kernel(const float* __restrict__ sinks) {
    extern __shared__ char sraw[];
    uint32_t sb = (smem_u32(sraw) + 1023u) & ~1023u;
    const uint32_t QB = sb, KVB = sb + 16384;

    const int qt = (int)gridDim.x - 1 - (int)blockIdx.x;
    const int h = blockIdx.y, kv = h & 7;
    const int tid = threadIdx.x, w = tid >> 5, lane = tid & 31;

    stage128q(QB, g_q_h + (size_t)(qt * 128) * QDIM + h * 64, QDIM, tid);
    stage_kv(KVB, 0, kv, tid);
    asm volatile("cp.async.commit_group;" ::: "memory");
    asm volatile("cp.async.wait_group 0;" ::: "memory");
    __syncthreads();

    uint32_t qh[2][4][4];
#pragma unroll
    for (int mt = 0; mt < 2; mt++) {
        int a_r = w * 32 + mt * 16 + (lane & 15);
        uint32_t ax = (uint32_t)((a_r & 7) << 4);
#pragma unroll
        for (int kt4 = 0; kt4 < 4; kt4++) {
            uint32_t cb = (uint32_t)(kt4 * 32 + ((lane >> 4) << 4));
            uint32_t off = (uint32_t)(a_r * 128) + (cb ^ ax);
            ldsm4(qh[mt][kt4], QB + off);
        }
    }

    float O[2][8][4];
#pragma unroll
    for (int mt = 0; mt < 2; mt++)
#pragma unroll
        for (int nt = 0; nt < 8; nt++)
#pragma unroll
            for (int j = 0; j < 4; j++) O[mt][nt][j] = 0.f;

    float snk = sinks[h];
    float mxA[2] = {snk, snk}, mxB[2] = {snk, snk};
    float lA[2] = {1.f, 1.f}, lB[2] = {1.f, 1.f};

    const int rbase = qt * 128 + w * 32 + (lane >> 2);
    const int b_rbase = ((lane >> 4) << 3) + (lane & 7);
    const uint32_t bsel = (uint32_t)(((lane >> 3) & 1) * 16);
    const int KT = 2 * qt + 2;

    for (int kt = 0; kt < KT; kt++) {
        if (kt + 1 < KT)
            stage_kv(KVB + ((kt + 1) & 1) * ATT_STAGE, kt + 1, kv, tid);
        asm volatile("cp.async.commit_group;" ::: "memory");
        asm volatile("cp.async.wait_group 1;" ::: "memory");
        __syncthreads();

        const uint32_t kb = KVB + (kt & 1) * ATT_STAGE;
        const uint32_t vb = kb + 8192;

        float sc[2][8][4];
#pragma unroll
        for (int mt = 0; mt < 2; mt++)
#pragma unroll
            for (int nt = 0; nt < 8; nt++)
#pragma unroll
                for (int j = 0; j < 4; j++) sc[mt][nt][j] = 0.f;

#pragma unroll
        for (int kt4 = 0; kt4 < 4; kt4++) {
#pragma unroll
            for (int kg = 0; kg < 4; kg++) {
                int b_r = kg * 16 + b_rbase;
                uint32_t off = (uint32_t)(b_r * 128) + (((uint32_t)(kt4 * 32) + bsel) ^ ((uint32_t)((b_r & 7) << 4)));
                uint32_t bh4[4];
                ldsm4(bh4, kb + off);
#pragma unroll
                for (int mt = 0; mt < 2; mt++) {
#pragma unroll
                    for (int n2 = 0; n2 < 2; n2++) {
                        mma_f16(sc[mt][2 * kg + n2], qh[mt][kt4], &bh4[n2 * 2]);
                    }
                }
            }
        }

        if (kt >= 2 * qt) {
#pragma unroll
            for (int mt = 0; mt < 2; mt++) {
                int row = rbase + mt * 16;
#pragma unroll
                for (int nt = 0; nt < 8; nt++) {
                    int key = kt * 64 + nt * 8 + 2 * (lane & 3);
                    if (key > row)         sc[mt][nt][0] = -1e30f;
                    if (key + 1 > row)     sc[mt][nt][1] = -1e30f;
                    if (key > row + 8)     sc[mt][nt][2] = -1e30f;
                    if (key + 1 > row + 8) sc[mt][nt][3] = -1e30f;
                }
            }
        }

#pragma unroll
        for (int mt = 0; mt < 2; mt++) {
            float r0 = -1e30f, r1 = -1e30f;
#pragma unroll
            for (int nt = 0; nt < 8; nt++) {
                r0 = fmaxf(r0, fmaxf(sc[mt][nt][0], sc[mt][nt][1]));
                r1 = fmaxf(r1, fmaxf(sc[mt][nt][2], sc[mt][nt][3]));
            }
            r0 = fmaxf(r0, __shfl_xor_sync(0xffffffffu, r0, 1));
            r0 = fmaxf(r0, __shfl_xor_sync(0xffffffffu, r0, 2));
            r1 = fmaxf(r1, __shfl_xor_sync(0xffffffffu, r1, 1));
            r1 = fmaxf(r1, __shfl_xor_sync(0xffffffffu, r1, 2));
            float mA2 = fmaxf(mxA[mt], r0), mB2 = fmaxf(mxB[mt], r1);
            float cA = __expf(mxA[mt] - mA2), cB = __expf(mxB[mt] - mB2);
            mxA[mt] = mA2; mxB[mt] = mB2;

            float sA = 0.f, sB = 0.f;
#pragma unroll
            for (int nt = 0; nt < 8; nt++) {
                sc[mt][nt][0] = __expf(sc[mt][nt][0] - mA2);
                sc[mt][nt][1] = __expf(sc[mt][nt][1] - mA2);
                sc[mt][nt][2] = __expf(sc[mt][nt][2] - mB2);
                sc[mt][nt][3] = __expf(sc[mt][nt][3] - mB2);
                sA += sc[mt][nt][0] + sc[mt][nt][1];
                sB += sc[mt][nt][2] + sc[mt][nt][3];
            }
            sA += __shfl_xor_sync(0xffffffffu, sA, 1);
            sA += __shfl_xor_sync(0xffffffffu, sA, 2);
            sB += __shfl_xor_sync(0xffffffffu, sB, 1);
            sB += __shfl_xor_sync(0xffffffffu, sB, 2);
            lA[mt] = lA[mt] * cA + sA;
            lB[mt] = lB[mt] * cB + sB;
#pragma unroll
            for (int nt = 0; nt < 8; nt++) {
                O[mt][nt][0] *= cA; O[mt][nt][1] *= cA;
                O[mt][nt][2] *= cB; O[mt][nt][3] *= cB;
            }
        }

#pragma unroll
        for (int sg = 0; sg < 4; sg++) {
            uint32_t ph[2][4];
#pragma unroll
            for (int mt = 0; mt < 2; mt++) {
                ph[mt][0] = pack_h2(sc[mt][2 * sg][0], sc[mt][2 * sg][1]);
                ph[mt][1] = pack_h2(sc[mt][2 * sg][2], sc[mt][2 * sg][3]);
                ph[mt][2] = pack_h2(sc[mt][2 * sg + 1][0], sc[mt][2 * sg + 1][1]);
                ph[mt][3] = pack_h2(sc[mt][2 * sg + 1][2], sc[mt][2 * sg + 1][3]);
            }
#pragma unroll
            for (int dg = 0; dg < 4; dg++) {
                int b_r = dg * 16 + b_rbase;
                uint32_t off = (uint32_t)(b_r * 128) + (((uint32_t)(sg * 32) + bsel) ^ ((uint32_t)((b_r & 7) << 4)));
                uint32_t vh4[4];
                ldsm4(vh4, vb + off);
#pragma unroll
                for (int mt = 0; mt < 2; mt++) {
#pragma unroll
                    for (int n2 = 0; n2 < 2; n2++) {
                        mma_f16(O[mt][2 * dg + n2], ph[mt], &vh4[n2 * 2]);
                    }
                }
            }
        }
        __syncthreads();
    }

#pragma unroll
    for (int mt = 0; mt < 2; mt++) {
        float iA = 1.f / lA[mt], iB = 1.f / lB[mt];
        int row = rbase + mt * 16;
        size_t r0o = (size_t)row * QDIM + h * 64;
        size_t r1o = r0o + (size_t)8 * QDIM;
#pragma unroll
        for (int nt = 0; nt < 8; nt++) {
            int c = nt * 8 + 2 * (lane & 3);
            *(uint32_t*)(g_o_h + r0o + c) = pack_h2(O[mt][nt][0] * iA, O[mt][nt][1] * iA);
            *(uint32_t*)(g_o_h + r1o + c) = pack_h2(O[mt][nt][2] * iB, O[mt][nt][3] * iB);
        }
    }
}

// ============================================================
// launch
// ============================================================
extern "C" void kernel_launch(void* const* d_in, const int* in_sizes, int n_in,
                              void* d_out, int out_size) {
    const float* x          = (const float*)d_in[0];
    const float* sinks      = (const float*)d_in[1];
    const float* norm_scale = (const float*)d_in[2];
    const float* qkv_w      = (const float*)d_in[3];
    const float* qkv_b      = (const float*)d_in[4];
    const float* out_w      = (const float*)d_in[5];
    const float* out_b      = (const float*)d_in[6];
    float* out = (float*)d_out;

    __half *th, *w1, *w2, *oh;
    cudaGetSymbolAddress((void**)&th, g_t_h);
    cudaGetSymbolAddress((void**)&w1, g_w1);
    cudaGetSymbolAddress((void**)&w2, g_w2);
    cudaGetSymbolAddress((void**)&oh, g_o_h);

    cudaFuncSetAttribute(gemm_mma<0>, cudaFuncAttributeMaxDynamicSharedMemorySize, SMEM_TOTAL_GEMM);
    cudaFuncSetAttribute(gemm_mma<1>, cudaFuncAttributeMaxDynamicSharedMemorySize, SMEM_TOTAL_GEMM);
    cudaFuncSetAttribute(attn_mma_kernel, cudaFuncAttributeMaxDynamicSharedMemorySize, ATT_SMEM_TOTAL);

    // rope tables FIRST (qkv epilogue consumes them)
    rope_tables_kernel<<<(S_TOK * 32 + 255) / 256, 256>>>();
    {
        int n4 = QKV_DIM * HID / 4;
        convert_h_kernel<<<(n4 + 255) / 256, 256>>>((const float4*)qkv_w, (uint2*)w1, n4);
    }
    {
        int n4 = HID * QDIM / 4;
        convert_h_kernel<<<(n4 + 255) / 256, 256>>>((const float4*)out_w, (uint2*)w2, n4);
    }

    rmsnorm_kernel<<<S_TOK, 256>>>(x, norm_scale);

    // qkv GEMM with fused bias+rope+scale epilogue -> g_q_h / g_k_h / g_vt_h
    gemm_mma<1><<<dim3(QKV_DIM / BN, S_TOK / BM), 128, SMEM_TOTAL_GEMM>>>(
        th, w1, qkv_b, nullptr, nullptr, S_TOK, QKV_DIM, HID);

    // tensorized attention (128-row q tiles)
    attn_mma_kernel<<<dim3(S_TOK / 128, NH), 128, ATT_SMEM_TOTAL>>>(sinks);

    // y = o @ out_w^T + out_b + x
    gemm_mma<0><<<dim3((HID + BN - 1) / BN, S_TOK / BM), 128, SMEM_TOTAL_GEMM>>>(
        oh, w2, out_b, x, out, S_TOK, HID, QDIM);
}